// round 10
// baseline (speedup 1.0000x reference)
#include <cuda_runtime.h>
#include <cuda_bf16.h>
#include <cstdint>

#define N_ROWS 32768
#define K_CODES 8192
#define D_DIM 512

#define BM 128
#define BN 128
#define BKE 64              // bf16 k-elems per tile
#define STAGES 3
#define NCHUNKS 64          // K_CODES / BN
#define KITERS 8            // D_DIM / BKE
#define TOTAL_T (NCHUNKS * KITERS)   // 512
#define RSU 36              // row stride in uint32 (64/2 + 4 pad) = 144 B
#define MARGIN 1.2e-3f
#define NSHARDS 64
#define SHARD_CAP 65536
#define FLT_MAX_BITS 0x7f7fffff

#define ZPAIRS (N_ROWS * D_DIM / 2)
#define EPAIRS (K_CODES * D_DIM / 2)

// ---------------- scratch (static __device__, no allocs) ----------------
__device__ float  g_znorm[N_ROWS];
__device__ float  g_enorm[K_CODES];
__device__ uint32_t g_zbf[ZPAIRS];   // packed bf16x2
__device__ uint32_t g_ebf[EPAIRS];
__device__ unsigned long long g_best[N_ROWS];
__device__ int    g_cand[NSHARDS][SHARD_CAP];
__device__ int    g_ncand[NSHARDS];
__device__ double g_rowpart[N_ROWS];

// ---------------- helpers ----------------
__device__ __forceinline__ uint32_t smem_u32(const void* p) {
    uint32_t a;
    asm("{ .reg .u64 t; cvta.to.shared.u64 t, %1; cvt.u32.u64 %0, t; }" : "=r"(a) : "l"(p));
    return a;
}
__device__ __forceinline__ void cpasync16(uint32_t dst, const void* src) {
    asm volatile("cp.async.cg.shared.global [%0], [%1], 16;" :: "r"(dst), "l"(src));
}
#define CP_COMMIT() asm volatile("cp.async.commit_group;" ::: "memory")
#define CP_WAITG1() asm volatile("cp.async.wait_group 1;" ::: "memory")
#define CP_WAIT0()  asm volatile("cp.async.wait_group 0;" ::: "memory")

#define LDSM_X4(r0, r1, r2, r3, addr) \
    asm volatile("ldmatrix.sync.aligned.m8n8.x4.shared.b16 {%0,%1,%2,%3}, [%4];" \
        : "=r"(r0), "=r"(r1), "=r"(r2), "=r"(r3) : "r"(addr))

// m16n8k16 bf16 HMMA (sm_80 base feature)
__device__ __forceinline__ void mma_bf16(float* d, const uint32_t* a, const uint32_t* b) {
    asm volatile("mma.sync.aligned.m16n8k16.row.col.f32.bf16.bf16.f32 "
        "{%0,%1,%2,%3}, {%4,%5,%6,%7}, {%8,%9}, {%0,%1,%2,%3};"
        : "+f"(d[0]), "+f"(d[1]), "+f"(d[2]), "+f"(d[3])
        : "r"(a[0]), "r"(a[1]), "r"(a[2]), "r"(a[3]), "r"(b[0]), "r"(b[1]));
}

// ---------------------------------------------------------------------------
__global__ void init_kernel() {
    int t = blockIdx.x * blockDim.x + threadIdx.x;
    if (t < NSHARDS) g_ncand[t] = 0;
    for (int i = t; i < N_ROWS; i += gridDim.x * blockDim.x)
        g_best[i] = 0xFFFFFFFFFFFFFFFFULL;
}

__global__ void convert_kernel(const float* __restrict__ Z, const float* __restrict__ E) {
    const int stride = gridDim.x * blockDim.x;
    int t = blockIdx.x * blockDim.x + threadIdx.x;
    for (int i = t; i < ZPAIRS; i += stride) {
        float2 v = reinterpret_cast<const float2*>(Z)[i];
        __nv_bfloat162 b = __floats2bfloat162_rn(v.x, v.y);
        g_zbf[i] = *reinterpret_cast<uint32_t*>(&b);
    }
    for (int i = t; i < EPAIRS; i += stride) {
        float2 v = reinterpret_cast<const float2*>(E)[i];
        __nv_bfloat162 b = __floats2bfloat162_rn(v.x, v.y);
        g_ebf[i] = *reinterpret_cast<uint32_t*>(&b);
    }
}

__global__ void norms_kernel(const float* __restrict__ z, const float* __restrict__ e) {
    int gw = (blockIdx.x * blockDim.x + threadIdx.x) >> 5;
    int lane = threadIdx.x & 31;
    if (gw >= N_ROWS + K_CODES) return;
    const float* p = (gw < N_ROWS) ? (z + (size_t)gw * D_DIM)
                                   : (e + (size_t)(gw - N_ROWS) * D_DIM);
    float acc = 0.0f;
    #pragma unroll
    for (int i = lane; i < D_DIM; i += 32) { float v = p[i]; acc = fmaf(v, v, acc); }
    #pragma unroll
    for (int o = 16; o > 0; o >>= 1) acc += __shfl_down_sync(0xffffffffu, acc, o);
    if (lane == 0) { if (gw < N_ROWS) g_znorm[gw] = acc; else g_enorm[gw - N_ROWS] = acc; }
}

// ---------------------------------------------------------------------------
// bf16 m16n8k16 GEMM + running per-row best + margin candidate push.
// Round-6 shape (128x128 CTA, warp 64x32, 8 warps, 2 CTAs/SM) with the
// (chunk, k) loops FLATTENED into one 512-iter pipeline: cp.async groups
// stay 2 deep across chunk boundaries -> no per-chunk drain/refill bubble.
// ---------------------------------------------------------------------------
__global__ __launch_bounds__(256, 2)
void vq_mma_kernel(const float* __restrict__, const float* __restrict__) {
    extern __shared__ uint32_t sm_u[];
    int* s_rowbest = reinterpret_cast<int*>(sm_u + STAGES * 2 * BM * RSU);

    const int tid = threadIdx.x;
    const int wid = tid >> 5;
    const int l   = tid & 31;
    const int warp_m = wid >> 2;        // 0..1
    const int warp_n = wid & 3;         // 0..3
    const int l4 = l >> 2;              // 0..7
    const int kc = l & 3;               // 0..3
    const int row0 = blockIdx.x * BM;
    const int shard = blockIdx.x & (NSHARDS - 1);

    const uint32_t sm_base  = smem_u32(sm_u);
    const int      stage_u  = 2 * BM * RSU;                 // u32 per stage
    const uint32_t stage_b  = (uint32_t)stage_u * 4;
    const uint32_t eoff_b   = (uint32_t)(BM * RSU) * 4;

    // ldmatrix per-lane byte offsets (within a stage)
    const uint32_t a_off = (uint32_t)((warp_m * 64 + (l & 15)) * RSU * 4 + ((l >> 4) * 16));
    const uint32_t b_off = (uint32_t)((warp_n * 32 + (l & 7) + ((l >> 4) << 3)) * RSU * 4
                                      + (((l >> 3) & 1) * 16)) + eoff_b;

    if (tid < BM) s_rowbest[tid] = FLT_MAX_BITS;

    float zn[8];
    #pragma unroll
    for (int mi = 0; mi < 4; mi++)
        #pragma unroll
        for (int hi = 0; hi < 2; hi++)
            zn[mi * 2 + hi] = g_znorm[row0 + warp_m * 64 + mi * 16 + hi * 8 + l4];

    __syncthreads();

    const int DP = D_DIM / 2;   // global row stride in pairs
    const uint32_t* Zg0 = g_zbf + (size_t)row0 * DP;

    float acc[4][4][4];

    // prologue: t=0,1 into stages 0,1
    #pragma unroll
    for (int pre = 0; pre < 2; pre++) {
        const int kp = pre * (BKE / 2);     // chunk 0
        const uint32_t zb = sm_base + (uint32_t)pre * stage_b;
        const uint32_t eb = zb + eoff_b;
        const uint32_t* Eg0 = g_ebf;        // chunk 0
        #pragma unroll
        for (int i = 0; i < 4; i++) {
            int u = tid + i * 256, r = u >> 3, s = u & 7;
            cpasync16(zb + r * (RSU * 4) + s * 16, Zg0 + (size_t)r * DP + kp + s * 4);
            cpasync16(eb + r * (RSU * 4) + s * 16, Eg0 + (size_t)r * DP + kp + s * 4);
        }
        CP_COMMIT();
    }

    for (int t = 0; t < TOTAL_T; t++) {
        const int c   = t >> 3;
        const int kit = t & 7;

        if (t == TOTAL_T - 1) { CP_WAIT0(); } else { CP_WAITG1(); }
        __syncthreads();

        if (t + 2 < TOTAL_T) {              // prefetch iter t+2 (may cross chunks)
            const int t2  = t + 2;
            const int c2  = t2 >> 3;
            const int kp  = (t2 & 7) * (BKE / 2);
            const uint32_t zb = sm_base + (uint32_t)(t2 % STAGES) * stage_b;
            const uint32_t eb = zb + eoff_b;
            const uint32_t* Eg0 = g_ebf + (size_t)(c2 * BN) * DP;
            #pragma unroll
            for (int i = 0; i < 4; i++) {
                int u = tid + i * 256, r = u >> 3, s = u & 7;
                cpasync16(zb + r * (RSU * 4) + s * 16, Zg0 + (size_t)r * DP + kp + s * 4);
                cpasync16(eb + r * (RSU * 4) + s * 16, Eg0 + (size_t)r * DP + kp + s * 4);
            }
            CP_COMMIT();
        }

        if (kit == 0) {
            #pragma unroll
            for (int mi = 0; mi < 4; mi++)
                #pragma unroll
                for (int ni = 0; ni < 4; ni++)
                    #pragma unroll
                    for (int r = 0; r < 4; r++) acc[mi][ni][r] = 0.0f;
        }

        // compute on stage t%3
        const uint32_t stg = sm_base + (uint32_t)(t % STAGES) * stage_b;
        const uint32_t abase = stg + a_off;
        const uint32_t bbase = stg + b_off;
        #pragma unroll
        for (int ks = 0; ks < 4; ks++) {
            uint32_t a[4][4], b[4][2];
            #pragma unroll
            for (int mi = 0; mi < 4; mi++)
                LDSM_X4(a[mi][0], a[mi][1], a[mi][2], a[mi][3],
                        abase + mi * (16 * RSU * 4) + ks * 32);
            #pragma unroll
            for (int np = 0; np < 2; np++)
                LDSM_X4(b[2 * np][0], b[2 * np][1], b[2 * np + 1][0], b[2 * np + 1][1],
                        bbase + np * (16 * RSU * 4) + ks * 32);
            #pragma unroll
            for (int mi = 0; mi < 4; mi++)
                #pragma unroll
                for (int ni = 0; ni < 4; ni++)
                    mma_bf16(acc[mi][ni], a[mi], b[ni]);
        }

        if (kit == KITERS - 1) {
            // ---------- epilogue pass 1: per-row running min ----------
            const int colg0 = c * BN + warp_n * 32 + kc * 2;
            float dmin[8];
            #pragma unroll
            for (int i = 0; i < 8; i++) dmin[i] = 3.4028235e38f;
            #pragma unroll
            for (int ni = 0; ni < 4; ni++) {
                float en0 = __ldg(&g_enorm[colg0 + ni * 8]);
                float en1 = __ldg(&g_enorm[colg0 + ni * 8 + 1]);
                #pragma unroll
                for (int mi = 0; mi < 4; mi++) {
                    float d0 = (zn[mi * 2] + en0)     - 2.0f * acc[mi][ni][0];
                    float d1 = (zn[mi * 2] + en1)     - 2.0f * acc[mi][ni][1];
                    float d2 = (zn[mi * 2 + 1] + en0) - 2.0f * acc[mi][ni][2];
                    float d3 = (zn[mi * 2 + 1] + en1) - 2.0f * acc[mi][ni][3];
                    dmin[mi * 2]     = fminf(dmin[mi * 2], fminf(d0, d1));
                    dmin[mi * 2 + 1] = fminf(dmin[mi * 2 + 1], fminf(d2, d3));
                }
            }
            #pragma unroll
            for (int i = 0; i < 8; i++) {
                dmin[i] = fminf(dmin[i], __shfl_xor_sync(0xffffffffu, dmin[i], 1));
                dmin[i] = fminf(dmin[i], __shfl_xor_sync(0xffffffffu, dmin[i], 2));
            }
            if (kc == 0) {
                #pragma unroll
                for (int mi = 0; mi < 4; mi++) {
                    atomicMin(&s_rowbest[warp_m * 64 + mi * 16 + l4],     __float_as_int(dmin[mi * 2]));
                    atomicMin(&s_rowbest[warp_m * 64 + mi * 16 + 8 + l4], __float_as_int(dmin[mi * 2 + 1]));
                }
            }
            __syncthreads();

            // ---------- epilogue pass 2: margin candidate push ----------
            #pragma unroll
            for (int ni = 0; ni < 4; ni++) {
                float en0 = __ldg(&g_enorm[colg0 + ni * 8]);
                float en1 = __ldg(&g_enorm[colg0 + ni * 8 + 1]);
                #pragma unroll
                for (int mi = 0; mi < 4; mi++) {
                    const int rl0 = warp_m * 64 + mi * 16 + l4;
                    const int rl1 = rl0 + 8;
                    const float b0 = __int_as_float(s_rowbest[rl0]) + MARGIN;
                    const float b1 = __int_as_float(s_rowbest[rl1]) + MARGIN;
                    float d0 = (zn[mi * 2] + en0)     - 2.0f * acc[mi][ni][0];
                    float d1 = (zn[mi * 2] + en1)     - 2.0f * acc[mi][ni][1];
                    float d2 = (zn[mi * 2 + 1] + en0) - 2.0f * acc[mi][ni][2];
                    float d3 = (zn[mi * 2 + 1] + en1) - 2.0f * acc[mi][ni][3];
                    if (d0 < b0) { int p = atomicAdd(&g_ncand[shard], 1);
                        if (p < SHARD_CAP) g_cand[shard][p] = ((row0 + rl0) << 13) | (colg0 + ni * 8); }
                    if (d1 < b0) { int p = atomicAdd(&g_ncand[shard], 1);
                        if (p < SHARD_CAP) g_cand[shard][p] = ((row0 + rl0) << 13) | (colg0 + ni * 8 + 1); }
                    if (d2 < b1) { int p = atomicAdd(&g_ncand[shard], 1);
                        if (p < SHARD_CAP) g_cand[shard][p] = ((row0 + rl1) << 13) | (colg0 + ni * 8); }
                    if (d3 < b1) { int p = atomicAdd(&g_ncand[shard], 1);
                        if (p < SHARD_CAP) g_cand[shard][p] = ((row0 + rl1) << 13) | (colg0 + ni * 8 + 1); }
                }
            }
        }
    }
}

// ---------------------------------------------------------------------------
__global__ void refine_kernel(const float* __restrict__ Z, const float* __restrict__ E) {
    const int nwarps = (gridDim.x * blockDim.x) >> 5;
    const int gw     = (blockIdx.x * blockDim.x + threadIdx.x) >> 5;
    const int lane   = threadIdx.x & 31;

    for (int s = 0; s < NSHARDS; s++) {
        int n = g_ncand[s];
        if (n > SHARD_CAP) n = SHARD_CAP;
        for (int i = gw; i < n; i += nwarps) {
            int cd  = g_cand[s][i];
            int row = cd >> 13;
            int idx = cd & (K_CODES - 1);
            const float4* z4 = reinterpret_cast<const float4*>(Z + (size_t)row * D_DIM);
            const float4* e4 = reinterpret_cast<const float4*>(E + (size_t)idx * D_DIM);
            float4 zv[4], ev[4];
            #pragma unroll
            for (int j = 0; j < 4; j++) {
                zv[j] = z4[j * 32 + lane];
                ev[j] = e4[j * 32 + lane];
            }
            float dot = 0.0f;
            #pragma unroll
            for (int j = 0; j < 4; j++) {
                dot = fmaf(zv[j].x, ev[j].x, dot);
                dot = fmaf(zv[j].y, ev[j].y, dot);
                dot = fmaf(zv[j].z, ev[j].z, dot);
                dot = fmaf(zv[j].w, ev[j].w, dot);
            }
            #pragma unroll
            for (int o = 16; o > 0; o >>= 1) dot += __shfl_down_sync(0xffffffffu, dot, o);
            if (lane == 0) {
                float d = (g_znorm[row] + g_enorm[idx]) - 2.0f * dot;
                unsigned long long key = ((unsigned long long)__float_as_uint(d) << 32) | (unsigned)idx;
                atomicMin(&g_best[row], key);
            }
        }
    }
}

// ---------------------------------------------------------------------------
__global__ void gather_kernel(const float* __restrict__ Z, const float* __restrict__ E,
                              float* __restrict__ out, int out_size) {
    int row = blockIdx.x;
    int t   = threadIdx.x;   // 128
    int idx = (int)(g_best[row] & 0xFFFFFFFFull) & (K_CODES - 1);
    const float* e = E + (size_t)idx * D_DIM;
    const float* z = Z + (size_t)row * D_DIM;
    float* o = out + (size_t)row * D_DIM;

    double s = 0.0;
    #pragma unroll
    for (int i = 0; i < 4; i++) {
        int d = t + i * 128;
        float q  = e[d];
        float zc = z[d];
        float dq = q - zc;
        o[d] = zc + dq;
        s += (double)dq * (double)dq;
    }
    __shared__ double sh[128];
    sh[t] = s;
    __syncthreads();
    for (int o2 = 64; o2 > 0; o2 >>= 1) { if (t < o2) sh[t] += sh[t + o2]; __syncthreads(); }
    if (t == 0) {
        g_rowpart[row] = sh[0];
        if (out_size >= N_ROWS * D_DIM + 1 + N_ROWS)
            out[(size_t)N_ROWS * D_DIM + 1 + row] = (float)idx;
    }
}

__global__ void loss_kernel(float* __restrict__ out, int out_size) {
    __shared__ double sh[256];
    int t = threadIdx.x;
    double s = 0.0;
    for (int i = t; i < N_ROWS; i += 256) s += g_rowpart[i];
    sh[t] = s;
    __syncthreads();
    for (int o = 128; o > 0; o >>= 1) { if (t < o) sh[t] += sh[t + o]; __syncthreads(); }
    if (t == 0 && out_size >= N_ROWS * D_DIM + 1) {
        double m = sh[0] / ((double)N_ROWS * (double)D_DIM);
        out[(size_t)N_ROWS * D_DIM] = (float)(1.25 * m);
    }
}

// ---------------------------------------------------------------------------
extern "C" void kernel_launch(void* const* d_in, const int* in_sizes, int n_in,
                              void* d_out, int out_size) {
    const float* z = (const float*)d_in[0];
    const float* e = (const float*)d_in[1];
    if (n_in >= 2 && in_sizes[0] == K_CODES * D_DIM && in_sizes[1] == N_ROWS * D_DIM) {
        const float* tmp = z; z = e; e = tmp;
    }
    float* out = (float*)d_out;

    const int smem_bytes = STAGES * 2 * BM * RSU * 4 + BM * 4;   // 111104
    cudaFuncSetAttribute(vq_mma_kernel, cudaFuncAttributeMaxDynamicSharedMemorySize, smem_bytes);

    init_kernel<<<256, 256>>>();
    convert_kernel<<<1024, 256>>>(z, e);
    int norm_blocks = ((N_ROWS + K_CODES) * 32 + 255) / 256;
    norms_kernel<<<norm_blocks, 256>>>(z, e);
    vq_mma_kernel<<<N_ROWS / BM, 256, smem_bytes>>>(z, e);
    refine_kernel<<<1024, 256>>>(z, e);
    gather_kernel<<<N_ROWS, 128>>>(z, e, out, out_size);
    loss_kernel<<<1, 256>>>(out, out_size);
}

// round 11
// speedup vs baseline: 1.2545x; 1.2545x over previous
#include <cuda_runtime.h>
#include <cuda_bf16.h>
#include <cstdint>

#define N_ROWS 32768
#define K_CODES 8192
#define D_DIM 512

#define BM 128
#define BN 128
#define BKE 64              // bf16 k-elems per tile
#define STAGES 3
#define NCHUNKS 64          // K_CODES / BN
#define KSPLIT 2            // chunk-range split for load balance
#define KITERS 8            // D_DIM / BKE
#define RSU 36              // row stride in uint32 (64/2 + 4 pad) = 144 B
#define MARGIN 1.2e-3f
#define NSHARDS 64
#define SHARD_CAP 65536
#define FLT_MAX_BITS 0x7f7fffff

#define ZPAIRS (N_ROWS * D_DIM / 2)
#define EPAIRS (K_CODES * D_DIM / 2)

// ---------------- scratch (static __device__, no allocs) ----------------
__device__ float  g_znorm[N_ROWS];
__device__ float  g_enorm[K_CODES];
__device__ uint32_t g_zbf[ZPAIRS];   // packed bf16x2
__device__ uint32_t g_ebf[EPAIRS];
__device__ unsigned long long g_best[N_ROWS];
__device__ int    g_cand[NSHARDS][SHARD_CAP];
__device__ int    g_ncand[NSHARDS];
__device__ double g_rowpart[N_ROWS];

// ---------------- helpers ----------------
__device__ __forceinline__ uint32_t smem_u32(const void* p) {
    uint32_t a;
    asm("{ .reg .u64 t; cvta.to.shared.u64 t, %1; cvt.u32.u64 %0, t; }" : "=r"(a) : "l"(p));
    return a;
}
__device__ __forceinline__ void cpasync16(uint32_t dst, const void* src) {
    asm volatile("cp.async.cg.shared.global [%0], [%1], 16;" :: "r"(dst), "l"(src));
}
#define CP_COMMIT() asm volatile("cp.async.commit_group;" ::: "memory")
#define CP_WAITG1() asm volatile("cp.async.wait_group 1;" ::: "memory")
#define CP_WAIT0()  asm volatile("cp.async.wait_group 0;" ::: "memory")

#define LDSM_X4(r0, r1, r2, r3, addr) \
    asm volatile("ldmatrix.sync.aligned.m8n8.x4.shared.b16 {%0,%1,%2,%3}, [%4];" \
        : "=r"(r0), "=r"(r1), "=r"(r2), "=r"(r3) : "r"(addr))

// m16n8k16 bf16 HMMA (sm_80 base feature)
__device__ __forceinline__ void mma_bf16(float* d, const uint32_t* a, const uint32_t* b) {
    asm volatile("mma.sync.aligned.m16n8k16.row.col.f32.bf16.bf16.f32 "
        "{%0,%1,%2,%3}, {%4,%5,%6,%7}, {%8,%9}, {%0,%1,%2,%3};"
        : "+f"(d[0]), "+f"(d[1]), "+f"(d[2]), "+f"(d[3])
        : "r"(a[0]), "r"(a[1]), "r"(a[2]), "r"(a[3]), "r"(b[0]), "r"(b[1]));
}

// ---------------------------------------------------------------------------
__global__ void init_kernel() {
    int t = blockIdx.x * blockDim.x + threadIdx.x;
    if (t < NSHARDS) g_ncand[t] = 0;
    for (int i = t; i < N_ROWS; i += gridDim.x * blockDim.x)
        g_best[i] = 0xFFFFFFFFFFFFFFFFULL;
}

// Fused: bf16 convert + row norms in a single pass (one warp per row).
__global__ void prep_kernel(const float* __restrict__ Z, const float* __restrict__ E) {
    int gw = (blockIdx.x * blockDim.x + threadIdx.x) >> 5;
    int lane = threadIdx.x & 31;
    if (gw >= N_ROWS + K_CODES) return;
    const float2* src;
    uint32_t* dst;
    if (gw < N_ROWS) {
        src = reinterpret_cast<const float2*>(Z + (size_t)gw * D_DIM);
        dst = g_zbf + (size_t)gw * (D_DIM / 2);
    } else {
        int r = gw - N_ROWS;
        src = reinterpret_cast<const float2*>(E + (size_t)r * D_DIM);
        dst = g_ebf + (size_t)r * (D_DIM / 2);
    }
    float acc = 0.0f;
    #pragma unroll
    for (int j = 0; j < 8; j++) {
        float2 v = src[j * 32 + lane];
        acc = fmaf(v.x, v.x, acc);
        acc = fmaf(v.y, v.y, acc);
        __nv_bfloat162 b = __floats2bfloat162_rn(v.x, v.y);
        dst[j * 32 + lane] = *reinterpret_cast<uint32_t*>(&b);
    }
    #pragma unroll
    for (int o = 16; o > 0; o >>= 1) acc += __shfl_down_sync(0xffffffffu, acc, o);
    if (lane == 0) {
        if (gw < N_ROWS) g_znorm[gw] = acc;
        else             g_enorm[gw - N_ROWS] = acc;
    }
}

// ---------------------------------------------------------------------------
// bf16 m16n8k16 GEMM + running per-row best + margin candidate push.
// Round-6 shape (128x128 CTA, warp 64x32, 8 warps, 2 CTAs/SM, 3-stage
// cp.async) with KSPLIT=2: each CTA covers half the chunk range so grid=512
// balances across the 296 CTA slots (grid 256 left ~40 SMs half idle).
// ---------------------------------------------------------------------------
__global__ __launch_bounds__(256, 2)
void vq_mma_kernel(const float* __restrict__, const float* __restrict__) {
    extern __shared__ uint32_t sm_u[];
    int* s_rowbest = reinterpret_cast<int*>(sm_u + STAGES * 2 * BM * RSU);

    const int tid = threadIdx.x;
    const int wid = tid >> 5;
    const int l   = tid & 31;
    const int warp_m = wid >> 2;        // 0..1
    const int warp_n = wid & 3;         // 0..3
    const int l4 = l >> 2;              // 0..7
    const int kc = l & 3;               // 0..3
    const int row0 = (blockIdx.x >> 1) * BM;
    const int c0   = (blockIdx.x & 1) * (NCHUNKS / KSPLIT);
    const int shard = blockIdx.x & (NSHARDS - 1);

    const uint32_t sm_base  = smem_u32(sm_u);
    const int      stage_u  = 2 * BM * RSU;                 // u32 per stage
    const uint32_t stage_b  = (uint32_t)stage_u * 4;
    const uint32_t eoff_b   = (uint32_t)(BM * RSU) * 4;

    // ldmatrix per-lane byte offsets (within a stage)
    const uint32_t a_off = (uint32_t)((warp_m * 64 + (l & 15)) * RSU * 4 + ((l >> 4) * 16));
    const uint32_t b_off = (uint32_t)((warp_n * 32 + (l & 7) + ((l >> 4) << 3)) * RSU * 4
                                      + (((l >> 3) & 1) * 16)) + eoff_b;

    if (tid < BM) s_rowbest[tid] = FLT_MAX_BITS;

    float zn[8];
    #pragma unroll
    for (int mi = 0; mi < 4; mi++)
        #pragma unroll
        for (int hi = 0; hi < 2; hi++)
            zn[mi * 2 + hi] = g_znorm[row0 + warp_m * 64 + mi * 16 + hi * 8 + l4];

    __syncthreads();

    const int DP = D_DIM / 2;   // global row stride in pairs

    for (int c = c0; c < c0 + NCHUNKS / KSPLIT; c++) {
        float acc[4][4][4];
        #pragma unroll
        for (int mi = 0; mi < 4; mi++)
            #pragma unroll
            for (int ni = 0; ni < 4; ni++)
                #pragma unroll
                for (int r = 0; r < 4; r++) acc[mi][ni][r] = 0.0f;

        const uint32_t* Zg0 = g_zbf + (size_t)row0 * DP;
        const uint32_t* Eg0 = g_ebf + (size_t)(c * BN) * DP;

        // prologue: k-iters 0,1 into stages 0,1
        #pragma unroll
        for (int pre = 0; pre < 2; pre++) {
            const int kp = pre * (BKE / 2);
            const uint32_t zb = sm_base + (uint32_t)pre * stage_b;
            const uint32_t eb = zb + eoff_b;
            #pragma unroll
            for (int i = 0; i < 4; i++) {
                int u = tid + i * 256, r = u >> 3, s = u & 7;
                cpasync16(zb + r * (RSU * 4) + s * 16, Zg0 + (size_t)r * DP + kp + s * 4);
                cpasync16(eb + r * (RSU * 4) + s * 16, Eg0 + (size_t)r * DP + kp + s * 4);
            }
            CP_COMMIT();
        }

        #pragma unroll
        for (int it = 0; it < KITERS; it++) {
            if (it == KITERS - 1) { CP_WAIT0(); } else { CP_WAITG1(); }
            __syncthreads();
            if (it + 2 < KITERS) {
                const int st = (it + 2) % STAGES;
                const int kp = (it + 2) * (BKE / 2);
                const uint32_t zb = sm_base + (uint32_t)st * stage_b;
                const uint32_t eb = zb + eoff_b;
                #pragma unroll
                for (int i = 0; i < 4; i++) {
                    int u = tid + i * 256, r = u >> 3, s = u & 7;
                    cpasync16(zb + r * (RSU * 4) + s * 16, Zg0 + (size_t)r * DP + kp + s * 4);
                    cpasync16(eb + r * (RSU * 4) + s * 16, Eg0 + (size_t)r * DP + kp + s * 4);
                }
                CP_COMMIT();
            }
            const uint32_t stg = sm_base + (uint32_t)(it % STAGES) * stage_b;
            const uint32_t abase = stg + a_off;
            const uint32_t bbase = stg + b_off;
            #pragma unroll
            for (int ks = 0; ks < 4; ks++) {
                uint32_t a[4][4], b[4][2];
                #pragma unroll
                for (int mi = 0; mi < 4; mi++)
                    LDSM_X4(a[mi][0], a[mi][1], a[mi][2], a[mi][3],
                            abase + mi * (16 * RSU * 4) + ks * 32);
                #pragma unroll
                for (int np = 0; np < 2; np++)
                    LDSM_X4(b[2 * np][0], b[2 * np][1], b[2 * np + 1][0], b[2 * np + 1][1],
                            bbase + np * (16 * RSU * 4) + ks * 32);
                #pragma unroll
                for (int mi = 0; mi < 4; mi++)
                    #pragma unroll
                    for (int ni = 0; ni < 4; ni++)
                        mma_bf16(acc[mi][ni], a[mi], b[ni]);
            }
        }

        // ---------- epilogue pass 1: per-row running min ----------
        const int colg0 = c * BN + warp_n * 32 + kc * 2;
        float dmin[8];
        #pragma unroll
        for (int i = 0; i < 8; i++) dmin[i] = 3.4028235e38f;
        #pragma unroll
        for (int ni = 0; ni < 4; ni++) {
            float en0 = __ldg(&g_enorm[colg0 + ni * 8]);
            float en1 = __ldg(&g_enorm[colg0 + ni * 8 + 1]);
            #pragma unroll
            for (int mi = 0; mi < 4; mi++) {
                float d0 = (zn[mi * 2] + en0)     - 2.0f * acc[mi][ni][0];
                float d1 = (zn[mi * 2] + en1)     - 2.0f * acc[mi][ni][1];
                float d2 = (zn[mi * 2 + 1] + en0) - 2.0f * acc[mi][ni][2];
                float d3 = (zn[mi * 2 + 1] + en1) - 2.0f * acc[mi][ni][3];
                dmin[mi * 2]     = fminf(dmin[mi * 2], fminf(d0, d1));
                dmin[mi * 2 + 1] = fminf(dmin[mi * 2 + 1], fminf(d2, d3));
            }
        }
        #pragma unroll
        for (int i = 0; i < 8; i++) {
            dmin[i] = fminf(dmin[i], __shfl_xor_sync(0xffffffffu, dmin[i], 1));
            dmin[i] = fminf(dmin[i], __shfl_xor_sync(0xffffffffu, dmin[i], 2));
        }
        if (kc == 0) {
            #pragma unroll
            for (int mi = 0; mi < 4; mi++) {
                atomicMin(&s_rowbest[warp_m * 64 + mi * 16 + l4],     __float_as_int(dmin[mi * 2]));
                atomicMin(&s_rowbest[warp_m * 64 + mi * 16 + 8 + l4], __float_as_int(dmin[mi * 2 + 1]));
            }
        }
        __syncthreads();   // orders it=7 compute before next prologue stores,
                           // and publishes rowbest for pass 2

        // ---------- epilogue pass 2: margin candidate push ----------
        #pragma unroll
        for (int ni = 0; ni < 4; ni++) {
            float en0 = __ldg(&g_enorm[colg0 + ni * 8]);
            float en1 = __ldg(&g_enorm[colg0 + ni * 8 + 1]);
            #pragma unroll
            for (int mi = 0; mi < 4; mi++) {
                const int rl0 = warp_m * 64 + mi * 16 + l4;
                const int rl1 = rl0 + 8;
                const float b0 = __int_as_float(s_rowbest[rl0]) + MARGIN;
                const float b1 = __int_as_float(s_rowbest[rl1]) + MARGIN;
                float d0 = (zn[mi * 2] + en0)     - 2.0f * acc[mi][ni][0];
                float d1 = (zn[mi * 2] + en1)     - 2.0f * acc[mi][ni][1];
                float d2 = (zn[mi * 2 + 1] + en0) - 2.0f * acc[mi][ni][2];
                float d3 = (zn[mi * 2 + 1] + en1) - 2.0f * acc[mi][ni][3];
                if (d0 < b0) { int p = atomicAdd(&g_ncand[shard], 1);
                    if (p < SHARD_CAP) g_cand[shard][p] = ((row0 + rl0) << 13) | (colg0 + ni * 8); }
                if (d1 < b0) { int p = atomicAdd(&g_ncand[shard], 1);
                    if (p < SHARD_CAP) g_cand[shard][p] = ((row0 + rl0) << 13) | (colg0 + ni * 8 + 1); }
                if (d2 < b1) { int p = atomicAdd(&g_ncand[shard], 1);
                    if (p < SHARD_CAP) g_cand[shard][p] = ((row0 + rl1) << 13) | (colg0 + ni * 8); }
                if (d3 < b1) { int p = atomicAdd(&g_ncand[shard], 1);
                    if (p < SHARD_CAP) g_cand[shard][p] = ((row0 + rl1) << 13) | (colg0 + ni * 8 + 1); }
            }
        }
    }
}

// ---------------------------------------------------------------------------
__global__ void refine_kernel(const float* __restrict__ Z, const float* __restrict__ E) {
    const int nwarps = (gridDim.x * blockDim.x) >> 5;
    const int gw     = (blockIdx.x * blockDim.x + threadIdx.x) >> 5;
    const int lane   = threadIdx.x & 31;

    for (int s = 0; s < NSHARDS; s++) {
        int n = g_ncand[s];
        if (n > SHARD_CAP) n = SHARD_CAP;
        for (int i = gw; i < n; i += nwarps) {
            int cd  = g_cand[s][i];
            int row = cd >> 13;
            int idx = cd & (K_CODES - 1);
            const float4* z4 = reinterpret_cast<const float4*>(Z + (size_t)row * D_DIM);
            const float4* e4 = reinterpret_cast<const float4*>(E + (size_t)idx * D_DIM);
            float4 zv[4], ev[4];
            #pragma unroll
            for (int j = 0; j < 4; j++) {
                zv[j] = z4[j * 32 + lane];
                ev[j] = e4[j * 32 + lane];
            }
            float dot = 0.0f;
            #pragma unroll
            for (int j = 0; j < 4; j++) {
                dot = fmaf(zv[j].x, ev[j].x, dot);
                dot = fmaf(zv[j].y, ev[j].y, dot);
                dot = fmaf(zv[j].z, ev[j].z, dot);
                dot = fmaf(zv[j].w, ev[j].w, dot);
            }
            #pragma unroll
            for (int o = 16; o > 0; o >>= 1) dot += __shfl_down_sync(0xffffffffu, dot, o);
            if (lane == 0) {
                float d = (g_znorm[row] + g_enorm[idx]) - 2.0f * dot;
                unsigned long long key = ((unsigned long long)__float_as_uint(d) << 32) | (unsigned)idx;
                atomicMin(&g_best[row], key);
            }
        }
    }
}

// ---------------------------------------------------------------------------
__global__ void gather_kernel(const float* __restrict__ Z, const float* __restrict__ E,
                              float* __restrict__ out, int out_size) {
    int row = blockIdx.x;
    int t   = threadIdx.x;   // 128
    int idx = (int)(g_best[row] & 0xFFFFFFFFull) & (K_CODES - 1);
    const float* e = E + (size_t)idx * D_DIM;
    const float* z = Z + (size_t)row * D_DIM;
    float* o = out + (size_t)row * D_DIM;

    double s = 0.0;
    #pragma unroll
    for (int i = 0; i < 4; i++) {
        int d = t + i * 128;
        float q  = e[d];
        float zc = z[d];
        float dq = q - zc;
        o[d] = zc + dq;
        s += (double)dq * (double)dq;
    }
    __shared__ double sh[128];
    sh[t] = s;
    __syncthreads();
    for (int o2 = 64; o2 > 0; o2 >>= 1) { if (t < o2) sh[t] += sh[t + o2]; __syncthreads(); }
    if (t == 0) {
        g_rowpart[row] = sh[0];
        if (out_size >= N_ROWS * D_DIM + 1 + N_ROWS)
            out[(size_t)N_ROWS * D_DIM + 1 + row] = (float)idx;
    }
}

__global__ void loss_kernel(float* __restrict__ out, int out_size) {
    __shared__ double sh[256];
    int t = threadIdx.x;
    double s = 0.0;
    for (int i = t; i < N_ROWS; i += 256) s += g_rowpart[i];
    sh[t] = s;
    __syncthreads();
    for (int o = 128; o > 0; o >>= 1) { if (t < o) sh[t] += sh[t + o]; __syncthreads(); }
    if (t == 0 && out_size >= N_ROWS * D_DIM + 1) {
        double m = sh[0] / ((double)N_ROWS * (double)D_DIM);
        out[(size_t)N_ROWS * D_DIM] = (float)(1.25 * m);
    }
}

// ---------------------------------------------------------------------------
extern "C" void kernel_launch(void* const* d_in, const int* in_sizes, int n_in,
                              void* d_out, int out_size) {
    const float* z = (const float*)d_in[0];
    const float* e = (const float*)d_in[1];
    if (n_in >= 2 && in_sizes[0] == K_CODES * D_DIM && in_sizes[1] == N_ROWS * D_DIM) {
        const float* tmp = z; z = e; e = tmp;
    }
    float* out = (float*)d_out;

    const int smem_bytes = STAGES * 2 * BM * RSU * 4 + BM * 4;   // 111104
    cudaFuncSetAttribute(vq_mma_kernel, cudaFuncAttributeMaxDynamicSharedMemorySize, smem_bytes);

    init_kernel<<<256, 256>>>();
    int prep_blocks = ((N_ROWS + K_CODES) * 32 + 255) / 256;     // one warp per row
    prep_kernel<<<prep_blocks, 256>>>(z, e);
    vq_mma_kernel<<<(N_ROWS / BM) * KSPLIT, 256, smem_bytes>>>(z, e);
    refine_kernel<<<1024, 256>>>(z, e);
    gather_kernel<<<N_ROWS, 128>>>(z, e, out, out_size);
    loss_kernel<<<1, 256>>>(out, out_size);
}

// round 12
// speedup vs baseline: 1.5548x; 1.2393x over previous
#include <cuda_runtime.h>
#include <cuda_bf16.h>
#include <cstdint>

#define N_ROWS 32768
#define K_CODES 8192
#define D_DIM 512

#define BM 128
#define BN 128
#define BKE 64              // bf16 k-elems per tile
#define STAGES 3
#define NCHUNKS 64          // K_CODES / BN
#define KSPLIT 4            // chunk-range split for load balance
#define KITERS 8            // D_DIM / BKE
#define RSU 36              // row stride in uint32 (64/2 + 4 pad) = 144 B
#define MARGIN 1.2e-3f
#define NSHARDS 64
#define SHARD_CAP 65536
#define FLT_MAX_BITS 0x7f7fffff

#define ZPAIRS (N_ROWS * D_DIM / 2)
#define EPAIRS (K_CODES * D_DIM / 2)

// ---------------- scratch (static __device__, no allocs) ----------------
__device__ float  g_znorm[N_ROWS];
__device__ float  g_enorm[K_CODES];
__device__ uint32_t g_zbf[ZPAIRS];   // packed bf16x2
__device__ uint32_t g_ebf[EPAIRS];
__device__ int    g_bound[N_ROWS];   // cross-CTA approx-distance bound (fp32 bits)
__device__ unsigned long long g_best[N_ROWS];
__device__ int    g_cand[NSHARDS][SHARD_CAP];
__device__ int    g_ncand[NSHARDS];
__device__ double g_rowpart[N_ROWS];

// ---------------- helpers ----------------
__device__ __forceinline__ uint32_t smem_u32(const void* p) {
    uint32_t a;
    asm("{ .reg .u64 t; cvta.to.shared.u64 t, %1; cvt.u32.u64 %0, t; }" : "=r"(a) : "l"(p));
    return a;
}
__device__ __forceinline__ void cpasync16(uint32_t dst, const void* src) {
    asm volatile("cp.async.cg.shared.global [%0], [%1], 16;" :: "r"(dst), "l"(src));
}
#define CP_COMMIT() asm volatile("cp.async.commit_group;" ::: "memory")
#define CP_WAITG1() asm volatile("cp.async.wait_group 1;" ::: "memory")
#define CP_WAIT0()  asm volatile("cp.async.wait_group 0;" ::: "memory")

#define LDSM_X4(r0, r1, r2, r3, addr) \
    asm volatile("ldmatrix.sync.aligned.m8n8.x4.shared.b16 {%0,%1,%2,%3}, [%4];" \
        : "=r"(r0), "=r"(r1), "=r"(r2), "=r"(r3) : "r"(addr))

// m16n8k16 bf16 HMMA (sm_80 base feature)
__device__ __forceinline__ void mma_bf16(float* d, const uint32_t* a, const uint32_t* b) {
    asm volatile("mma.sync.aligned.m16n8k16.row.col.f32.bf16.bf16.f32 "
        "{%0,%1,%2,%3}, {%4,%5,%6,%7}, {%8,%9}, {%0,%1,%2,%3};"
        : "+f"(d[0]), "+f"(d[1]), "+f"(d[2]), "+f"(d[3])
        : "r"(a[0]), "r"(a[1]), "r"(a[2]), "r"(a[3]), "r"(b[0]), "r"(b[1]));
}

// ---------------------------------------------------------------------------
__global__ void init_kernel() {
    int t = blockIdx.x * blockDim.x + threadIdx.x;
    if (t < NSHARDS) g_ncand[t] = 0;
    for (int i = t; i < N_ROWS; i += gridDim.x * blockDim.x) {
        g_best[i]  = 0xFFFFFFFFFFFFFFFFULL;
        g_bound[i] = FLT_MAX_BITS;
    }
}

// Fused: bf16 convert + row norms in a single pass (one warp per row).
__global__ void prep_kernel(const float* __restrict__ Z, const float* __restrict__ E) {
    int gw = (blockIdx.x * blockDim.x + threadIdx.x) >> 5;
    int lane = threadIdx.x & 31;
    if (gw >= N_ROWS + K_CODES) return;
    const float2* src;
    uint32_t* dst;
    if (gw < N_ROWS) {
        src = reinterpret_cast<const float2*>(Z + (size_t)gw * D_DIM);
        dst = g_zbf + (size_t)gw * (D_DIM / 2);
    } else {
        int r = gw - N_ROWS;
        src = reinterpret_cast<const float2*>(E + (size_t)r * D_DIM);
        dst = g_ebf + (size_t)r * (D_DIM / 2);
    }
    float acc = 0.0f;
    #pragma unroll
    for (int j = 0; j < 8; j++) {
        float2 v = src[j * 32 + lane];
        acc = fmaf(v.x, v.x, acc);
        acc = fmaf(v.y, v.y, acc);
        __nv_bfloat162 b = __floats2bfloat162_rn(v.x, v.y);
        dst[j * 32 + lane] = *reinterpret_cast<uint32_t*>(&b);
    }
    #pragma unroll
    for (int o = 16; o > 0; o >>= 1) acc += __shfl_down_sync(0xffffffffu, acc, o);
    if (lane == 0) {
        if (gw < N_ROWS) g_znorm[gw] = acc;
        else             g_enorm[gw - N_ROWS] = acc;
    }
}

// ---------------------------------------------------------------------------
// bf16 m16n8k16 GEMM + running per-row best + margin candidate push.
// Round-6 shape (128x128 CTA, warp 64x32, 8 warps, 2 CTAs/SM, 3-stage
// cp.async). KSPLIT=4 (grid 1024) for tail smoothing; per-row bounds are
// merged through a global atomicMin so later CTAs prune with the best
// approx distance seen anywhere on the chip.
// ---------------------------------------------------------------------------
__global__ __launch_bounds__(256, 2)
void vq_mma_kernel(const float* __restrict__, const float* __restrict__) {
    extern __shared__ uint32_t sm_u[];
    int* s_rowbest = reinterpret_cast<int*>(sm_u + STAGES * 2 * BM * RSU);

    const int tid = threadIdx.x;
    const int wid = tid >> 5;
    const int l   = tid & 31;
    const int warp_m = wid >> 2;        // 0..1
    const int warp_n = wid & 3;         // 0..3
    const int l4 = l >> 2;              // 0..7
    const int kc = l & 3;               // 0..3
    const int row0 = (blockIdx.x >> 2) * BM;
    const int c0   = (blockIdx.x & 3) * (NCHUNKS / KSPLIT);
    const int shard = blockIdx.x & (NSHARDS - 1);

    const uint32_t sm_base  = smem_u32(sm_u);
    const int      stage_u  = 2 * BM * RSU;                 // u32 per stage
    const uint32_t stage_b  = (uint32_t)stage_u * 4;
    const uint32_t eoff_b   = (uint32_t)(BM * RSU) * 4;

    // ldmatrix per-lane byte offsets (within a stage)
    const uint32_t a_off = (uint32_t)((warp_m * 64 + (l & 15)) * RSU * 4 + ((l >> 4) * 16));
    const uint32_t b_off = (uint32_t)((warp_n * 32 + (l & 7) + ((l >> 4) << 3)) * RSU * 4
                                      + (((l >> 3) & 1) * 16)) + eoff_b;

    if (tid < BM) s_rowbest[tid] = FLT_MAX_BITS;

    float zn[8];
    #pragma unroll
    for (int mi = 0; mi < 4; mi++)
        #pragma unroll
        for (int hi = 0; hi < 2; hi++)
            zn[mi * 2 + hi] = g_znorm[row0 + warp_m * 64 + mi * 16 + hi * 8 + l4];

    __syncthreads();

    const int DP = D_DIM / 2;   // global row stride in pairs

    for (int c = c0; c < c0 + NCHUNKS / KSPLIT; c++) {
        float acc[4][4][4];
        #pragma unroll
        for (int mi = 0; mi < 4; mi++)
            #pragma unroll
            for (int ni = 0; ni < 4; ni++)
                #pragma unroll
                for (int r = 0; r < 4; r++) acc[mi][ni][r] = 0.0f;

        const uint32_t* Zg0 = g_zbf + (size_t)row0 * DP;
        const uint32_t* Eg0 = g_ebf + (size_t)(c * BN) * DP;

        // prologue: k-iters 0,1 into stages 0,1
        #pragma unroll
        for (int pre = 0; pre < 2; pre++) {
            const int kp = pre * (BKE / 2);
            const uint32_t zb = sm_base + (uint32_t)pre * stage_b;
            const uint32_t eb = zb + eoff_b;
            #pragma unroll
            for (int i = 0; i < 4; i++) {
                int u = tid + i * 256, r = u >> 3, s = u & 7;
                cpasync16(zb + r * (RSU * 4) + s * 16, Zg0 + (size_t)r * DP + kp + s * 4);
                cpasync16(eb + r * (RSU * 4) + s * 16, Eg0 + (size_t)r * DP + kp + s * 4);
            }
            CP_COMMIT();
        }

        #pragma unroll
        for (int it = 0; it < KITERS; it++) {
            if (it == KITERS - 1) { CP_WAIT0(); } else { CP_WAITG1(); }
            __syncthreads();
            if (it + 2 < KITERS) {
                const int st = (it + 2) % STAGES;
                const int kp = (it + 2) * (BKE / 2);
                const uint32_t zb = sm_base + (uint32_t)st * stage_b;
                const uint32_t eb = zb + eoff_b;
                #pragma unroll
                for (int i = 0; i < 4; i++) {
                    int u = tid + i * 256, r = u >> 3, s = u & 7;
                    cpasync16(zb + r * (RSU * 4) + s * 16, Zg0 + (size_t)r * DP + kp + s * 4);
                    cpasync16(eb + r * (RSU * 4) + s * 16, Eg0 + (size_t)r * DP + kp + s * 4);
                }
                CP_COMMIT();
            }
            const uint32_t stg = sm_base + (uint32_t)(it % STAGES) * stage_b;
            const uint32_t abase = stg + a_off;
            const uint32_t bbase = stg + b_off;
            #pragma unroll
            for (int ks = 0; ks < 4; ks++) {
                uint32_t a[4][4], b[4][2];
                #pragma unroll
                for (int mi = 0; mi < 4; mi++)
                    LDSM_X4(a[mi][0], a[mi][1], a[mi][2], a[mi][3],
                            abase + mi * (16 * RSU * 4) + ks * 32);
                #pragma unroll
                for (int np = 0; np < 2; np++)
                    LDSM_X4(b[2 * np][0], b[2 * np][1], b[2 * np + 1][0], b[2 * np + 1][1],
                            bbase + np * (16 * RSU * 4) + ks * 32);
                #pragma unroll
                for (int mi = 0; mi < 4; mi++)
                    #pragma unroll
                    for (int ni = 0; ni < 4; ni++)
                        mma_bf16(acc[mi][ni], a[mi], b[ni]);
            }
        }

        // ---------- epilogue pass 1: per-row running min + global merge ----------
        const int colg0 = c * BN + warp_n * 32 + kc * 2;
        float dmin[8];
        #pragma unroll
        for (int i = 0; i < 8; i++) dmin[i] = 3.4028235e38f;
        #pragma unroll
        for (int ni = 0; ni < 4; ni++) {
            float en0 = __ldg(&g_enorm[colg0 + ni * 8]);
            float en1 = __ldg(&g_enorm[colg0 + ni * 8 + 1]);
            #pragma unroll
            for (int mi = 0; mi < 4; mi++) {
                float d0 = (zn[mi * 2] + en0)     - 2.0f * acc[mi][ni][0];
                float d1 = (zn[mi * 2] + en1)     - 2.0f * acc[mi][ni][1];
                float d2 = (zn[mi * 2 + 1] + en0) - 2.0f * acc[mi][ni][2];
                float d3 = (zn[mi * 2 + 1] + en1) - 2.0f * acc[mi][ni][3];
                dmin[mi * 2]     = fminf(dmin[mi * 2], fminf(d0, d1));
                dmin[mi * 2 + 1] = fminf(dmin[mi * 2 + 1], fminf(d2, d3));
            }
        }
        #pragma unroll
        for (int i = 0; i < 8; i++) {
            dmin[i] = fminf(dmin[i], __shfl_xor_sync(0xffffffffu, dmin[i], 1));
            dmin[i] = fminf(dmin[i], __shfl_xor_sync(0xffffffffu, dmin[i], 2));
        }
        if (kc == 0) {
            #pragma unroll
            for (int mi = 0; mi < 4; mi++) {
                const int rl0 = warp_m * 64 + mi * 16 + l4;
                const int rl1 = rl0 + 8;
                int b0 = __float_as_int(dmin[mi * 2]);
                int b1 = __float_as_int(dmin[mi * 2 + 1]);
                // global atomicMin returns the old value: free cross-CTA bound
                int og0 = atomicMin(&g_bound[row0 + rl0], b0);
                int og1 = atomicMin(&g_bound[row0 + rl1], b1);
                atomicMin(&s_rowbest[rl0], min(og0, b0));
                atomicMin(&s_rowbest[rl1], min(og1, b1));
            }
        }
        __syncthreads();   // orders it=7 compute before next prologue stores,
                           // and publishes rowbest for pass 2

        // ---------- epilogue pass 2: margin candidate push ----------
        #pragma unroll
        for (int ni = 0; ni < 4; ni++) {
            float en0 = __ldg(&g_enorm[colg0 + ni * 8]);
            float en1 = __ldg(&g_enorm[colg0 + ni * 8 + 1]);
            #pragma unroll
            for (int mi = 0; mi < 4; mi++) {
                const int rl0 = warp_m * 64 + mi * 16 + l4;
                const int rl1 = rl0 + 8;
                const float b0 = __int_as_float(s_rowbest[rl0]) + MARGIN;
                const float b1 = __int_as_float(s_rowbest[rl1]) + MARGIN;
                float d0 = (zn[mi * 2] + en0)     - 2.0f * acc[mi][ni][0];
                float d1 = (zn[mi * 2] + en1)     - 2.0f * acc[mi][ni][1];
                float d2 = (zn[mi * 2 + 1] + en0) - 2.0f * acc[mi][ni][2];
                float d3 = (zn[mi * 2 + 1] + en1) - 2.0f * acc[mi][ni][3];
                if (d0 < b0) { int p = atomicAdd(&g_ncand[shard], 1);
                    if (p < SHARD_CAP) g_cand[shard][p] = ((row0 + rl0) << 13) | (colg0 + ni * 8); }
                if (d1 < b0) { int p = atomicAdd(&g_ncand[shard], 1);
                    if (p < SHARD_CAP) g_cand[shard][p] = ((row0 + rl0) << 13) | (colg0 + ni * 8 + 1); }
                if (d2 < b1) { int p = atomicAdd(&g_ncand[shard], 1);
                    if (p < SHARD_CAP) g_cand[shard][p] = ((row0 + rl1) << 13) | (colg0 + ni * 8); }
                if (d3 < b1) { int p = atomicAdd(&g_ncand[shard], 1);
                    if (p < SHARD_CAP) g_cand[shard][p] = ((row0 + rl1) << 13) | (colg0 + ni * 8 + 1); }
            }
        }
    }
}

// ---------------------------------------------------------------------------
__global__ void refine_kernel(const float* __restrict__ Z, const float* __restrict__ E) {
    const int nwarps = (gridDim.x * blockDim.x) >> 5;
    const int gw     = (blockIdx.x * blockDim.x + threadIdx.x) >> 5;
    const int lane   = threadIdx.x & 31;

    for (int s = 0; s < NSHARDS; s++) {
        int n = g_ncand[s];
        if (n > SHARD_CAP) n = SHARD_CAP;
        for (int i = gw; i < n; i += nwarps) {
            int cd  = g_cand[s][i];
            int row = cd >> 13;
            int idx = cd & (K_CODES - 1);
            const float4* z4 = reinterpret_cast<const float4*>(Z + (size_t)row * D_DIM);
            const float4* e4 = reinterpret_cast<const float4*>(E + (size_t)idx * D_DIM);
            float4 zv[4], ev[4];
            #pragma unroll
            for (int j = 0; j < 4; j++) {
                zv[j] = z4[j * 32 + lane];
                ev[j] = e4[j * 32 + lane];
            }
            float dot = 0.0f;
            #pragma unroll
            for (int j = 0; j < 4; j++) {
                dot = fmaf(zv[j].x, ev[j].x, dot);
                dot = fmaf(zv[j].y, ev[j].y, dot);
                dot = fmaf(zv[j].z, ev[j].z, dot);
                dot = fmaf(zv[j].w, ev[j].w, dot);
            }
            #pragma unroll
            for (int o = 16; o > 0; o >>= 1) dot += __shfl_down_sync(0xffffffffu, dot, o);
            if (lane == 0) {
                float d = (g_znorm[row] + g_enorm[idx]) - 2.0f * dot;
                unsigned long long key = ((unsigned long long)__float_as_uint(d) << 32) | (unsigned)idx;
                atomicMin(&g_best[row], key);
            }
        }
    }
}

// ---------------------------------------------------------------------------
__global__ void gather_kernel(const float* __restrict__ Z, const float* __restrict__ E,
                              float* __restrict__ out, int out_size) {
    int row = blockIdx.x;
    int t   = threadIdx.x;   // 128 -> one float4 per thread (D=512)
    int idx = (int)(g_best[row] & 0xFFFFFFFFull) & (K_CODES - 1);
    const float4* e4 = reinterpret_cast<const float4*>(E + (size_t)idx * D_DIM);
    const float4* z4 = reinterpret_cast<const float4*>(Z + (size_t)row * D_DIM);
    float4* o4 = reinterpret_cast<float4*>(out + (size_t)row * D_DIM);

    float4 q = e4[t], zc = z4[t], dq, o;
    dq.x = q.x - zc.x; dq.y = q.y - zc.y; dq.z = q.z - zc.z; dq.w = q.w - zc.w;
    o.x = zc.x + dq.x; o.y = zc.y + dq.y; o.z = zc.z + dq.z; o.w = zc.w + dq.w;
    o4[t] = o;
    double s = (double)dq.x * dq.x + (double)dq.y * dq.y
             + (double)dq.z * dq.z + (double)dq.w * dq.w;

    __shared__ double sh[128];
    sh[t] = s;
    __syncthreads();
    for (int o2 = 64; o2 > 0; o2 >>= 1) { if (t < o2) sh[t] += sh[t + o2]; __syncthreads(); }
    if (t == 0) {
        g_rowpart[row] = sh[0];
        if (out_size >= N_ROWS * D_DIM + 1 + N_ROWS)
            out[(size_t)N_ROWS * D_DIM + 1 + row] = (float)idx;
    }
}

__global__ void loss_kernel(float* __restrict__ out, int out_size) {
    __shared__ double sh[256];
    int t = threadIdx.x;
    double s = 0.0;
    for (int i = t; i < N_ROWS; i += 256) s += g_rowpart[i];
    sh[t] = s;
    __syncthreads();
    for (int o = 128; o > 0; o >>= 1) { if (t < o) sh[t] += sh[t + o]; __syncthreads(); }
    if (t == 0 && out_size >= N_ROWS * D_DIM + 1) {
        double m = sh[0] / ((double)N_ROWS * (double)D_DIM);
        out[(size_t)N_ROWS * D_DIM] = (float)(1.25 * m);
    }
}

// ---------------------------------------------------------------------------
extern "C" void kernel_launch(void* const* d_in, const int* in_sizes, int n_in,
                              void* d_out, int out_size) {
    const float* z = (const float*)d_in[0];
    const float* e = (const float*)d_in[1];
    if (n_in >= 2 && in_sizes[0] == K_CODES * D_DIM && in_sizes[1] == N_ROWS * D_DIM) {
        const float* tmp = z; z = e; e = tmp;
    }
    float* out = (float*)d_out;

    const int smem_bytes = STAGES * 2 * BM * RSU * 4 + BM * 4;   // 111104
    cudaFuncSetAttribute(vq_mma_kernel, cudaFuncAttributeMaxDynamicSharedMemorySize, smem_bytes);

    init_kernel<<<256, 256>>>();
    int prep_blocks = ((N_ROWS + K_CODES) * 32 + 255) / 256;     // one warp per row
    prep_kernel<<<prep_blocks, 256>>>(z, e);
    vq_mma_kernel<<<(N_ROWS / BM) * KSPLIT, 256, smem_bytes>>>(z, e);
    refine_kernel<<<1024, 256>>>(z, e);
    gather_kernel<<<N_ROWS, 128>>>(z, e, out, out_size);
    loss_kernel<<<1, 256>>>(out, out_size);
}

// round 13
// speedup vs baseline: 1.6838x; 1.0830x over previous
#include <cuda_runtime.h>
#include <cuda_bf16.h>
#include <cstdint>

#define N_ROWS 32768
#define K_CODES 8192
#define D_DIM 512

#define BM 128
#define BN 128
#define BKE 64              // bf16 k-elems per tile
#define STAGES 3
#define NCHUNKS 64          // K_CODES / BN
#define KSPLIT 8            // chunk-range split for load balance (grid 2048)
#define KITERS 8            // D_DIM / BKE
#define RSU 36              // row stride in uint32 (64/2 + 4 pad) = 144 B
#define MARGIN 1.2e-3f
#define NSHARDS 64
#define SHARD_CAP 65536
#define FLT_MAX_BITS 0x7f7fffff

#define ZPAIRS (N_ROWS * D_DIM / 2)
#define EPAIRS (K_CODES * D_DIM / 2)

// ---------------- scratch (static __device__, no allocs) ----------------
__device__ float  g_znorm[N_ROWS];
__device__ float  g_enorm[K_CODES];
__device__ uint32_t g_zbf[ZPAIRS];   // packed bf16x2
__device__ uint32_t g_ebf[EPAIRS];
__device__ int    g_bound[N_ROWS];   // cross-CTA approx-distance bound (fp32 bits)
__device__ unsigned long long g_best[N_ROWS];
__device__ int    g_cand[NSHARDS][SHARD_CAP];
__device__ float  g_cand_d[NSHARDS][SHARD_CAP];   // approx distance at push time
__device__ int    g_ncand[NSHARDS];
__device__ double g_rowpart[N_ROWS];

// ---------------- helpers ----------------
__device__ __forceinline__ uint32_t smem_u32(const void* p) {
    uint32_t a;
    asm("{ .reg .u64 t; cvta.to.shared.u64 t, %1; cvt.u32.u64 %0, t; }" : "=r"(a) : "l"(p));
    return a;
}
__device__ __forceinline__ void cpasync16(uint32_t dst, const void* src) {
    asm volatile("cp.async.cg.shared.global [%0], [%1], 16;" :: "r"(dst), "l"(src));
}
#define CP_COMMIT() asm volatile("cp.async.commit_group;" ::: "memory")
#define CP_WAITG1() asm volatile("cp.async.wait_group 1;" ::: "memory")
#define CP_WAIT0()  asm volatile("cp.async.wait_group 0;" ::: "memory")

#define LDSM_X4(r0, r1, r2, r3, addr) \
    asm volatile("ldmatrix.sync.aligned.m8n8.x4.shared.b16 {%0,%1,%2,%3}, [%4];" \
        : "=r"(r0), "=r"(r1), "=r"(r2), "=r"(r3) : "r"(addr))

// m16n8k16 bf16 HMMA (sm_80 base feature)
__device__ __forceinline__ void mma_bf16(float* d, const uint32_t* a, const uint32_t* b) {
    asm volatile("mma.sync.aligned.m16n8k16.row.col.f32.bf16.bf16.f32 "
        "{%0,%1,%2,%3}, {%4,%5,%6,%7}, {%8,%9}, {%0,%1,%2,%3};"
        : "+f"(d[0]), "+f"(d[1]), "+f"(d[2]), "+f"(d[3])
        : "r"(a[0]), "r"(a[1]), "r"(a[2]), "r"(a[3]), "r"(b[0]), "r"(b[1]));
}

// ---------------------------------------------------------------------------
__global__ void init_kernel() {
    int t = blockIdx.x * blockDim.x + threadIdx.x;
    if (t < NSHARDS) g_ncand[t] = 0;
    for (int i = t; i < N_ROWS; i += gridDim.x * blockDim.x) {
        g_best[i]  = 0xFFFFFFFFFFFFFFFFULL;
        g_bound[i] = FLT_MAX_BITS;
    }
}

// Fused: bf16 convert + row norms in a single pass (one warp per row).
__global__ void prep_kernel(const float* __restrict__ Z, const float* __restrict__ E) {
    int gw = (blockIdx.x * blockDim.x + threadIdx.x) >> 5;
    int lane = threadIdx.x & 31;
    if (gw >= N_ROWS + K_CODES) return;
    const float2* src;
    uint32_t* dst;
    if (gw < N_ROWS) {
        src = reinterpret_cast<const float2*>(Z + (size_t)gw * D_DIM);
        dst = g_zbf + (size_t)gw * (D_DIM / 2);
    } else {
        int r = gw - N_ROWS;
        src = reinterpret_cast<const float2*>(E + (size_t)r * D_DIM);
        dst = g_ebf + (size_t)r * (D_DIM / 2);
    }
    float acc = 0.0f;
    #pragma unroll
    for (int j = 0; j < 8; j++) {
        float2 v = src[j * 32 + lane];
        acc = fmaf(v.x, v.x, acc);
        acc = fmaf(v.y, v.y, acc);
        __nv_bfloat162 b = __floats2bfloat162_rn(v.x, v.y);
        dst[j * 32 + lane] = *reinterpret_cast<uint32_t*>(&b);
    }
    #pragma unroll
    for (int o = 16; o > 0; o >>= 1) acc += __shfl_down_sync(0xffffffffu, acc, o);
    if (lane == 0) {
        if (gw < N_ROWS) g_znorm[gw] = acc;
        else             g_enorm[gw - N_ROWS] = acc;
    }
}

// ---------------------------------------------------------------------------
// bf16 m16n8k16 GEMM + running per-row best + margin candidate push.
// Round-6 shape (128x128 CTA, warp 64x32, 8 warps, 2 CTAs/SM, 3-stage
// cp.async). KSPLIT=8 (grid 2048 -> 6.9 waves, last wave 92% full vs 46%
// at KSPLIT=4). Cross-CTA atomicMin bound pruning; pushes record d-hat.
// ---------------------------------------------------------------------------
__global__ __launch_bounds__(256, 2)
void vq_mma_kernel(const float* __restrict__, const float* __restrict__) {
    extern __shared__ uint32_t sm_u[];
    int* s_rowbest = reinterpret_cast<int*>(sm_u + STAGES * 2 * BM * RSU);

    const int tid = threadIdx.x;
    const int wid = tid >> 5;
    const int l   = tid & 31;
    const int warp_m = wid >> 2;        // 0..1
    const int warp_n = wid & 3;         // 0..3
    const int l4 = l >> 2;              // 0..7
    const int kc = l & 3;               // 0..3
    const int row0 = (blockIdx.x >> 3) * BM;
    const int c0   = (blockIdx.x & 7) * (NCHUNKS / KSPLIT);
    const int shard = blockIdx.x & (NSHARDS - 1);

    const uint32_t sm_base  = smem_u32(sm_u);
    const int      stage_u  = 2 * BM * RSU;                 // u32 per stage
    const uint32_t stage_b  = (uint32_t)stage_u * 4;
    const uint32_t eoff_b   = (uint32_t)(BM * RSU) * 4;

    // ldmatrix per-lane byte offsets (within a stage)
    const uint32_t a_off = (uint32_t)((warp_m * 64 + (l & 15)) * RSU * 4 + ((l >> 4) * 16));
    const uint32_t b_off = (uint32_t)((warp_n * 32 + (l & 7) + ((l >> 4) << 3)) * RSU * 4
                                      + (((l >> 3) & 1) * 16)) + eoff_b;

    if (tid < BM) s_rowbest[tid] = FLT_MAX_BITS;

    float zn[8];
    #pragma unroll
    for (int mi = 0; mi < 4; mi++)
        #pragma unroll
        for (int hi = 0; hi < 2; hi++)
            zn[mi * 2 + hi] = g_znorm[row0 + warp_m * 64 + mi * 16 + hi * 8 + l4];

    __syncthreads();

    const int DP = D_DIM / 2;   // global row stride in pairs

    for (int c = c0; c < c0 + NCHUNKS / KSPLIT; c++) {
        float acc[4][4][4];
        #pragma unroll
        for (int mi = 0; mi < 4; mi++)
            #pragma unroll
            for (int ni = 0; ni < 4; ni++)
                #pragma unroll
                for (int r = 0; r < 4; r++) acc[mi][ni][r] = 0.0f;

        const uint32_t* Zg0 = g_zbf + (size_t)row0 * DP;
        const uint32_t* Eg0 = g_ebf + (size_t)(c * BN) * DP;

        // prologue: k-iters 0,1 into stages 0,1
        #pragma unroll
        for (int pre = 0; pre < 2; pre++) {
            const int kp = pre * (BKE / 2);
            const uint32_t zb = sm_base + (uint32_t)pre * stage_b;
            const uint32_t eb = zb + eoff_b;
            #pragma unroll
            for (int i = 0; i < 4; i++) {
                int u = tid + i * 256, r = u >> 3, s = u & 7;
                cpasync16(zb + r * (RSU * 4) + s * 16, Zg0 + (size_t)r * DP + kp + s * 4);
                cpasync16(eb + r * (RSU * 4) + s * 16, Eg0 + (size_t)r * DP + kp + s * 4);
            }
            CP_COMMIT();
        }

        #pragma unroll
        for (int it = 0; it < KITERS; it++) {
            if (it == KITERS - 1) { CP_WAIT0(); } else { CP_WAITG1(); }
            __syncthreads();
            if (it + 2 < KITERS) {
                const int st = (it + 2) % STAGES;
                const int kp = (it + 2) * (BKE / 2);
                const uint32_t zb = sm_base + (uint32_t)st * stage_b;
                const uint32_t eb = zb + eoff_b;
                #pragma unroll
                for (int i = 0; i < 4; i++) {
                    int u = tid + i * 256, r = u >> 3, s = u & 7;
                    cpasync16(zb + r * (RSU * 4) + s * 16, Zg0 + (size_t)r * DP + kp + s * 4);
                    cpasync16(eb + r * (RSU * 4) + s * 16, Eg0 + (size_t)r * DP + kp + s * 4);
                }
                CP_COMMIT();
            }
            const uint32_t stg = sm_base + (uint32_t)(it % STAGES) * stage_b;
            const uint32_t abase = stg + a_off;
            const uint32_t bbase = stg + b_off;
            #pragma unroll
            for (int ks = 0; ks < 4; ks++) {
                uint32_t a[4][4], b[4][2];
                #pragma unroll
                for (int mi = 0; mi < 4; mi++)
                    LDSM_X4(a[mi][0], a[mi][1], a[mi][2], a[mi][3],
                            abase + mi * (16 * RSU * 4) + ks * 32);
                #pragma unroll
                for (int np = 0; np < 2; np++)
                    LDSM_X4(b[2 * np][0], b[2 * np][1], b[2 * np + 1][0], b[2 * np + 1][1],
                            bbase + np * (16 * RSU * 4) + ks * 32);
                #pragma unroll
                for (int mi = 0; mi < 4; mi++)
                    #pragma unroll
                    for (int ni = 0; ni < 4; ni++)
                        mma_bf16(acc[mi][ni], a[mi], b[ni]);
            }
        }

        // ---------- epilogue pass 1: per-row running min + global merge ----------
        const int colg0 = c * BN + warp_n * 32 + kc * 2;
        float dmin[8];
        #pragma unroll
        for (int i = 0; i < 8; i++) dmin[i] = 3.4028235e38f;
        #pragma unroll
        for (int ni = 0; ni < 4; ni++) {
            float en0 = __ldg(&g_enorm[colg0 + ni * 8]);
            float en1 = __ldg(&g_enorm[colg0 + ni * 8 + 1]);
            #pragma unroll
            for (int mi = 0; mi < 4; mi++) {
                float d0 = (zn[mi * 2] + en0)     - 2.0f * acc[mi][ni][0];
                float d1 = (zn[mi * 2] + en1)     - 2.0f * acc[mi][ni][1];
                float d2 = (zn[mi * 2 + 1] + en0) - 2.0f * acc[mi][ni][2];
                float d3 = (zn[mi * 2 + 1] + en1) - 2.0f * acc[mi][ni][3];
                dmin[mi * 2]     = fminf(dmin[mi * 2], fminf(d0, d1));
                dmin[mi * 2 + 1] = fminf(dmin[mi * 2 + 1], fminf(d2, d3));
            }
        }
        #pragma unroll
        for (int i = 0; i < 8; i++) {
            dmin[i] = fminf(dmin[i], __shfl_xor_sync(0xffffffffu, dmin[i], 1));
            dmin[i] = fminf(dmin[i], __shfl_xor_sync(0xffffffffu, dmin[i], 2));
        }
        if (kc == 0) {
            #pragma unroll
            for (int mi = 0; mi < 4; mi++) {
                const int rl0 = warp_m * 64 + mi * 16 + l4;
                const int rl1 = rl0 + 8;
                int b0 = __float_as_int(dmin[mi * 2]);
                int b1 = __float_as_int(dmin[mi * 2 + 1]);
                // global atomicMin returns the old value: free cross-CTA bound
                int og0 = atomicMin(&g_bound[row0 + rl0], b0);
                int og1 = atomicMin(&g_bound[row0 + rl1], b1);
                atomicMin(&s_rowbest[rl0], min(og0, b0));
                atomicMin(&s_rowbest[rl1], min(og1, b1));
            }
        }
        __syncthreads();   // orders it=7 compute before next prologue stores,
                           // and publishes rowbest for pass 2

        // ---------- epilogue pass 2: margin candidate push (records d-hat) ----------
        #pragma unroll
        for (int ni = 0; ni < 4; ni++) {
            float en0 = __ldg(&g_enorm[colg0 + ni * 8]);
            float en1 = __ldg(&g_enorm[colg0 + ni * 8 + 1]);
            #pragma unroll
            for (int mi = 0; mi < 4; mi++) {
                const int rl0 = warp_m * 64 + mi * 16 + l4;
                const int rl1 = rl0 + 8;
                const float b0 = __int_as_float(s_rowbest[rl0]) + MARGIN;
                const float b1 = __int_as_float(s_rowbest[rl1]) + MARGIN;
                float d0 = (zn[mi * 2] + en0)     - 2.0f * acc[mi][ni][0];
                float d1 = (zn[mi * 2] + en1)     - 2.0f * acc[mi][ni][1];
                float d2 = (zn[mi * 2 + 1] + en0) - 2.0f * acc[mi][ni][2];
                float d3 = (zn[mi * 2 + 1] + en1) - 2.0f * acc[mi][ni][3];
                if (d0 < b0) { int p = atomicAdd(&g_ncand[shard], 1);
                    if (p < SHARD_CAP) { g_cand[shard][p] = ((row0 + rl0) << 13) | (colg0 + ni * 8);
                                         g_cand_d[shard][p] = d0; } }
                if (d1 < b0) { int p = atomicAdd(&g_ncand[shard], 1);
                    if (p < SHARD_CAP) { g_cand[shard][p] = ((row0 + rl0) << 13) | (colg0 + ni * 8 + 1);
                                         g_cand_d[shard][p] = d1; } }
                if (d2 < b1) { int p = atomicAdd(&g_ncand[shard], 1);
                    if (p < SHARD_CAP) { g_cand[shard][p] = ((row0 + rl1) << 13) | (colg0 + ni * 8);
                                         g_cand_d[shard][p] = d2; } }
                if (d3 < b1) { int p = atomicAdd(&g_ncand[shard], 1);
                    if (p < SHARD_CAP) { g_cand[shard][p] = ((row0 + rl1) << 13) | (colg0 + ni * 8 + 1);
                                         g_cand_d[shard][p] = d3; } }
            }
        }
    }
}

// ---------------------------------------------------------------------------
// Exact fp32 refinement with FINAL-bound pre-pruning: candidates pushed
// before the global bound converged are skipped without touching row data.
// ---------------------------------------------------------------------------
__global__ void refine_kernel(const float* __restrict__ Z, const float* __restrict__ E) {
    const int nwarps = (gridDim.x * blockDim.x) >> 5;
    const int gw     = (blockIdx.x * blockDim.x + threadIdx.x) >> 5;
    const int lane   = threadIdx.x & 31;

    for (int s = 0; s < NSHARDS; s++) {
        int n = g_ncand[s];
        if (n > SHARD_CAP) n = SHARD_CAP;
        for (int i = gw; i < n; i += nwarps) {
            int cd  = g_cand[s][i];
            int row = cd >> 13;
            int idx = cd & (K_CODES - 1);
            // prune against the fully-converged bound (vq_mma finished)
            float dhat  = g_cand_d[s][i];
            float bound = __int_as_float(g_bound[row]);
            if (dhat > bound + MARGIN) continue;

            const float4* z4 = reinterpret_cast<const float4*>(Z + (size_t)row * D_DIM);
            const float4* e4 = reinterpret_cast<const float4*>(E + (size_t)idx * D_DIM);
            float4 zv[4], ev[4];
            #pragma unroll
            for (int j = 0; j < 4; j++) {
                zv[j] = z4[j * 32 + lane];
                ev[j] = e4[j * 32 + lane];
            }
            float dot = 0.0f;
            #pragma unroll
            for (int j = 0; j < 4; j++) {
                dot = fmaf(zv[j].x, ev[j].x, dot);
                dot = fmaf(zv[j].y, ev[j].y, dot);
                dot = fmaf(zv[j].z, ev[j].z, dot);
                dot = fmaf(zv[j].w, ev[j].w, dot);
            }
            #pragma unroll
            for (int o = 16; o > 0; o >>= 1) dot += __shfl_down_sync(0xffffffffu, dot, o);
            if (lane == 0) {
                float d = (g_znorm[row] + g_enorm[idx]) - 2.0f * dot;
                unsigned long long key = ((unsigned long long)__float_as_uint(d) << 32) | (unsigned)idx;
                atomicMin(&g_best[row], key);
            }
        }
    }
}

// ---------------------------------------------------------------------------
__global__ void gather_kernel(const float* __restrict__ Z, const float* __restrict__ E,
                              float* __restrict__ out, int out_size) {
    int row = blockIdx.x;
    int t   = threadIdx.x;   // 128 -> one float4 per thread (D=512)
    int idx = (int)(g_best[row] & 0xFFFFFFFFull) & (K_CODES - 1);
    const float4* e4 = reinterpret_cast<const float4*>(E + (size_t)idx * D_DIM);
    const float4* z4 = reinterpret_cast<const float4*>(Z + (size_t)row * D_DIM);
    float4* o4 = reinterpret_cast<float4*>(out + (size_t)row * D_DIM);

    float4 q = e4[t], zc = z4[t], dq, o;
    dq.x = q.x - zc.x; dq.y = q.y - zc.y; dq.z = q.z - zc.z; dq.w = q.w - zc.w;
    o.x = zc.x + dq.x; o.y = zc.y + dq.y; o.z = zc.z + dq.z; o.w = zc.w + dq.w;
    o4[t] = o;
    double s = (double)dq.x * dq.x + (double)dq.y * dq.y
             + (double)dq.z * dq.z + (double)dq.w * dq.w;

    __shared__ double sh[128];
    sh[t] = s;
    __syncthreads();
    for (int o2 = 64; o2 > 0; o2 >>= 1) { if (t < o2) sh[t] += sh[t + o2]; __syncthreads(); }
    if (t == 0) {
        g_rowpart[row] = sh[0];
        if (out_size >= N_ROWS * D_DIM + 1 + N_ROWS)
            out[(size_t)N_ROWS * D_DIM + 1 + row] = (float)idx;
    }
}

__global__ void loss_kernel(float* __restrict__ out, int out_size) {
    __shared__ double sh[256];
    int t = threadIdx.x;
    double s = 0.0;
    for (int i = t; i < N_ROWS; i += 256) s += g_rowpart[i];
    sh[t] = s;
    __syncthreads();
    for (int o = 128; o > 0; o >>= 1) { if (t < o) sh[t] += sh[t + o]; __syncthreads(); }
    if (t == 0 && out_size >= N_ROWS * D_DIM + 1) {
        double m = sh[0] / ((double)N_ROWS * (double)D_DIM);
        out[(size_t)N_ROWS * D_DIM] = (float)(1.25 * m);
    }
}

// ---------------------------------------------------------------------------
extern "C" void kernel_launch(void* const* d_in, const int* in_sizes, int n_in,
                              void* d_out, int out_size) {
    const float* z = (const float*)d_in[0];
    const float* e = (const float*)d_in[1];
    if (n_in >= 2 && in_sizes[0] == K_CODES * D_DIM && in_sizes[1] == N_ROWS * D_DIM) {
        const float* tmp = z; z = e; e = tmp;
    }
    float* out = (float*)d_out;

    const int smem_bytes = STAGES * 2 * BM * RSU * 4 + BM * 4;   // 111104
    cudaFuncSetAttribute(vq_mma_kernel, cudaFuncAttributeMaxDynamicSharedMemorySize, smem_bytes);

    init_kernel<<<256, 256>>>();
    int prep_blocks = ((N_ROWS + K_CODES) * 32 + 255) / 256;     // one warp per row
    prep_kernel<<<prep_blocks, 256>>>(z, e);
    vq_mma_kernel<<<(N_ROWS / BM) * KSPLIT, 256, smem_bytes>>>(z, e);
    refine_kernel<<<1024, 256>>>(z, e);
    gather_kernel<<<N_ROWS, 128>>>(z, e, out, out_size);
    loss_kernel<<<1, 256>>>(out, out_size);
}

// round 14
// speedup vs baseline: 1.7501x; 1.0394x over previous
#include <cuda_runtime.h>
#include <cuda_bf16.h>
#include <cstdint>

#define N_ROWS 32768
#define K_CODES 8192
#define D_DIM 512

#define BM 128
#define BN 128
#define BKE 64              // bf16 k-elems per tile
#define STAGES 3
#define NCHUNKS 64          // K_CODES / BN
#define KSPLIT 8            // chunk-range split for load balance (grid 2048)
#define KITERS 8            // D_DIM / BKE
#define RSU 36              // row stride in uint32 (64/2 + 4 pad) = 144 B
#define MARGIN 1.2e-3f
#define NSHARDS 64
#define SHARD_CAP 65536
#define FLT_MAX_BITS 0x7f7fffff

#define ZPAIRS (N_ROWS * D_DIM / 2)
#define EPAIRS (K_CODES * D_DIM / 2)

// ---------------- scratch (static __device__, no allocs) ----------------
__device__ float  g_znorm[N_ROWS];
__device__ float  g_enorm[K_CODES];
__device__ uint32_t g_zbf[ZPAIRS];   // packed bf16x2
__device__ uint32_t g_ebf[EPAIRS];
__device__ int    g_bound[N_ROWS];   // cross-CTA approx-distance bound (fp32 bits)
__device__ unsigned long long g_best[N_ROWS];
__device__ int    g_cand[NSHARDS][SHARD_CAP];
__device__ float  g_cand_d[NSHARDS][SHARD_CAP];   // approx distance at push time
__device__ int    g_ncand[NSHARDS];
__device__ double g_rowpart[N_ROWS];

// ---------------- helpers ----------------
__device__ __forceinline__ uint32_t smem_u32(const void* p) {
    uint32_t a;
    asm("{ .reg .u64 t; cvta.to.shared.u64 t, %1; cvt.u32.u64 %0, t; }" : "=r"(a) : "l"(p));
    return a;
}
__device__ __forceinline__ void cpasync16(uint32_t dst, const void* src) {
    asm volatile("cp.async.cg.shared.global [%0], [%1], 16;" :: "r"(dst), "l"(src));
}
#define CP_COMMIT() asm volatile("cp.async.commit_group;" ::: "memory")
#define CP_WAITG1() asm volatile("cp.async.wait_group 1;" ::: "memory")
#define CP_WAIT0()  asm volatile("cp.async.wait_group 0;" ::: "memory")

#define LDSM_X4(r0, r1, r2, r3, addr) \
    asm volatile("ldmatrix.sync.aligned.m8n8.x4.shared.b16 {%0,%1,%2,%3}, [%4];" \
        : "=r"(r0), "=r"(r1), "=r"(r2), "=r"(r3) : "r"(addr))

// m16n8k16 bf16 HMMA (sm_80 base feature)
__device__ __forceinline__ void mma_bf16(float* d, const uint32_t* a, const uint32_t* b) {
    asm volatile("mma.sync.aligned.m16n8k16.row.col.f32.bf16.bf16.f32 "
        "{%0,%1,%2,%3}, {%4,%5,%6,%7}, {%8,%9}, {%0,%1,%2,%3};"
        : "+f"(d[0]), "+f"(d[1]), "+f"(d[2]), "+f"(d[3])
        : "r"(a[0]), "r"(a[1]), "r"(a[2]), "r"(a[3]), "r"(b[0]), "r"(b[1]));
}

// ---------------------------------------------------------------------------
// Fused: scratch init + bf16 convert + row norms in one pass.
// One warp per row (N+K rows); thread-parallel init of g_best/g_bound/g_ncand.
// ---------------------------------------------------------------------------
__global__ void prep_kernel(const float* __restrict__ Z, const float* __restrict__ E) {
    const int gtid = blockIdx.x * blockDim.x + threadIdx.x;
    if (gtid < N_ROWS) {
        g_best[gtid]  = 0xFFFFFFFFFFFFFFFFULL;
        g_bound[gtid] = FLT_MAX_BITS;
    }
    if (gtid < NSHARDS) g_ncand[gtid] = 0;

    int gw = gtid >> 5;
    int lane = threadIdx.x & 31;
    if (gw >= N_ROWS + K_CODES) return;
    const float2* src;
    uint32_t* dst;
    if (gw < N_ROWS) {
        src = reinterpret_cast<const float2*>(Z + (size_t)gw * D_DIM);
        dst = g_zbf + (size_t)gw * (D_DIM / 2);
    } else {
        int r = gw - N_ROWS;
        src = reinterpret_cast<const float2*>(E + (size_t)r * D_DIM);
        dst = g_ebf + (size_t)r * (D_DIM / 2);
    }
    float acc = 0.0f;
    #pragma unroll
    for (int j = 0; j < 8; j++) {
        float2 v = src[j * 32 + lane];
        acc = fmaf(v.x, v.x, acc);
        acc = fmaf(v.y, v.y, acc);
        __nv_bfloat162 b = __floats2bfloat162_rn(v.x, v.y);
        dst[j * 32 + lane] = *reinterpret_cast<uint32_t*>(&b);
    }
    #pragma unroll
    for (int o = 16; o > 0; o >>= 1) acc += __shfl_down_sync(0xffffffffu, acc, o);
    if (lane == 0) {
        if (gw < N_ROWS) g_znorm[gw] = acc;
        else             g_enorm[gw - N_ROWS] = acc;
    }
}

// ---------------------------------------------------------------------------
// bf16 m16n8k16 GEMM + running per-row best + margin candidate push.
// 128x128 CTA, warp 64x32, 8 warps, 2 CTAs/SM, 3-stage cp.async, KSPLIT=8
// (grid 2048, 6.9 waves, 1% quantization waste). Cross-CTA atomicMin bound
// pruning; pushes record d-hat for final-bound re-pruning in refine.
// ---------------------------------------------------------------------------
__global__ __launch_bounds__(256, 2)
void vq_mma_kernel(const float* __restrict__, const float* __restrict__) {
    extern __shared__ uint32_t sm_u[];
    int* s_rowbest = reinterpret_cast<int*>(sm_u + STAGES * 2 * BM * RSU);

    const int tid = threadIdx.x;
    const int wid = tid >> 5;
    const int l   = tid & 31;
    const int warp_m = wid >> 2;        // 0..1
    const int warp_n = wid & 3;         // 0..3
    const int l4 = l >> 2;              // 0..7
    const int kc = l & 3;               // 0..3
    const int row0 = (blockIdx.x >> 3) * BM;
    const int c0   = (blockIdx.x & 7) * (NCHUNKS / KSPLIT);
    const int shard = blockIdx.x & (NSHARDS - 1);

    const uint32_t sm_base  = smem_u32(sm_u);
    const int      stage_u  = 2 * BM * RSU;                 // u32 per stage
    const uint32_t stage_b  = (uint32_t)stage_u * 4;
    const uint32_t eoff_b   = (uint32_t)(BM * RSU) * 4;

    // ldmatrix per-lane byte offsets (within a stage)
    const uint32_t a_off = (uint32_t)((warp_m * 64 + (l & 15)) * RSU * 4 + ((l >> 4) * 16));
    const uint32_t b_off = (uint32_t)((warp_n * 32 + (l & 7) + ((l >> 4) << 3)) * RSU * 4
                                      + (((l >> 3) & 1) * 16)) + eoff_b;

    if (tid < BM) s_rowbest[tid] = FLT_MAX_BITS;

    float zn[8];
    #pragma unroll
    for (int mi = 0; mi < 4; mi++)
        #pragma unroll
        for (int hi = 0; hi < 2; hi++)
            zn[mi * 2 + hi] = g_znorm[row0 + warp_m * 64 + mi * 16 + hi * 8 + l4];

    __syncthreads();

    const int DP = D_DIM / 2;   // global row stride in pairs

    for (int c = c0; c < c0 + NCHUNKS / KSPLIT; c++) {
        float acc[4][4][4];
        #pragma unroll
        for (int mi = 0; mi < 4; mi++)
            #pragma unroll
            for (int ni = 0; ni < 4; ni++)
                #pragma unroll
                for (int r = 0; r < 4; r++) acc[mi][ni][r] = 0.0f;

        const uint32_t* Zg0 = g_zbf + (size_t)row0 * DP;
        const uint32_t* Eg0 = g_ebf + (size_t)(c * BN) * DP;

        // prologue: k-iters 0,1 into stages 0,1
        #pragma unroll
        for (int pre = 0; pre < 2; pre++) {
            const int kp = pre * (BKE / 2);
            const uint32_t zb = sm_base + (uint32_t)pre * stage_b;
            const uint32_t eb = zb + eoff_b;
            #pragma unroll
            for (int i = 0; i < 4; i++) {
                int u = tid + i * 256, r = u >> 3, s = u & 7;
                cpasync16(zb + r * (RSU * 4) + s * 16, Zg0 + (size_t)r * DP + kp + s * 4);
                cpasync16(eb + r * (RSU * 4) + s * 16, Eg0 + (size_t)r * DP + kp + s * 4);
            }
            CP_COMMIT();
        }

        #pragma unroll
        for (int it = 0; it < KITERS; it++) {
            if (it == KITERS - 1) { CP_WAIT0(); } else { CP_WAITG1(); }
            __syncthreads();
            if (it + 2 < KITERS) {
                const int st = (it + 2) % STAGES;
                const int kp = (it + 2) * (BKE / 2);
                const uint32_t zb = sm_base + (uint32_t)st * stage_b;
                const uint32_t eb = zb + eoff_b;
                #pragma unroll
                for (int i = 0; i < 4; i++) {
                    int u = tid + i * 256, r = u >> 3, s = u & 7;
                    cpasync16(zb + r * (RSU * 4) + s * 16, Zg0 + (size_t)r * DP + kp + s * 4);
                    cpasync16(eb + r * (RSU * 4) + s * 16, Eg0 + (size_t)r * DP + kp + s * 4);
                }
                CP_COMMIT();
            }
            const uint32_t stg = sm_base + (uint32_t)(it % STAGES) * stage_b;
            const uint32_t abase = stg + a_off;
            const uint32_t bbase = stg + b_off;
            #pragma unroll
            for (int ks = 0; ks < 4; ks++) {
                uint32_t a[4][4], b[4][2];
                #pragma unroll
                for (int mi = 0; mi < 4; mi++)
                    LDSM_X4(a[mi][0], a[mi][1], a[mi][2], a[mi][3],
                            abase + mi * (16 * RSU * 4) + ks * 32);
                #pragma unroll
                for (int np = 0; np < 2; np++)
                    LDSM_X4(b[2 * np][0], b[2 * np][1], b[2 * np + 1][0], b[2 * np + 1][1],
                            bbase + np * (16 * RSU * 4) + ks * 32);
                #pragma unroll
                for (int mi = 0; mi < 4; mi++)
                    #pragma unroll
                    for (int ni = 0; ni < 4; ni++)
                        mma_bf16(acc[mi][ni], a[mi], b[ni]);
            }
        }

        // ---------- epilogue pass 1: per-row running min + global merge ----------
        const int colg0 = c * BN + warp_n * 32 + kc * 2;
        float dmin[8];
        #pragma unroll
        for (int i = 0; i < 8; i++) dmin[i] = 3.4028235e38f;
        #pragma unroll
        for (int ni = 0; ni < 4; ni++) {
            float en0 = __ldg(&g_enorm[colg0 + ni * 8]);
            float en1 = __ldg(&g_enorm[colg0 + ni * 8 + 1]);
            #pragma unroll
            for (int mi = 0; mi < 4; mi++) {
                float d0 = (zn[mi * 2] + en0)     - 2.0f * acc[mi][ni][0];
                float d1 = (zn[mi * 2] + en1)     - 2.0f * acc[mi][ni][1];
                float d2 = (zn[mi * 2 + 1] + en0) - 2.0f * acc[mi][ni][2];
                float d3 = (zn[mi * 2 + 1] + en1) - 2.0f * acc[mi][ni][3];
                dmin[mi * 2]     = fminf(dmin[mi * 2], fminf(d0, d1));
                dmin[mi * 2 + 1] = fminf(dmin[mi * 2 + 1], fminf(d2, d3));
            }
        }
        #pragma unroll
        for (int i = 0; i < 8; i++) {
            dmin[i] = fminf(dmin[i], __shfl_xor_sync(0xffffffffu, dmin[i], 1));
            dmin[i] = fminf(dmin[i], __shfl_xor_sync(0xffffffffu, dmin[i], 2));
        }
        if (kc == 0) {
            #pragma unroll
            for (int mi = 0; mi < 4; mi++) {
                const int rl0 = warp_m * 64 + mi * 16 + l4;
                const int rl1 = rl0 + 8;
                int b0 = __float_as_int(dmin[mi * 2]);
                int b1 = __float_as_int(dmin[mi * 2 + 1]);
                // global atomicMin returns the old value: free cross-CTA bound
                int og0 = atomicMin(&g_bound[row0 + rl0], b0);
                int og1 = atomicMin(&g_bound[row0 + rl1], b1);
                atomicMin(&s_rowbest[rl0], min(og0, b0));
                atomicMin(&s_rowbest[rl1], min(og1, b1));
            }
        }
        __syncthreads();   // orders it=7 compute before next prologue stores,
                           // and publishes rowbest for pass 2

        // ---------- epilogue pass 2: margin candidate push (records d-hat) ----------
        #pragma unroll
        for (int ni = 0; ni < 4; ni++) {
            float en0 = __ldg(&g_enorm[colg0 + ni * 8]);
            float en1 = __ldg(&g_enorm[colg0 + ni * 8 + 1]);
            #pragma unroll
            for (int mi = 0; mi < 4; mi++) {
                const int rl0 = warp_m * 64 + mi * 16 + l4;
                const int rl1 = rl0 + 8;
                const float b0 = __int_as_float(s_rowbest[rl0]) + MARGIN;
                const float b1 = __int_as_float(s_rowbest[rl1]) + MARGIN;
                float d0 = (zn[mi * 2] + en0)     - 2.0f * acc[mi][ni][0];
                float d1 = (zn[mi * 2] + en1)     - 2.0f * acc[mi][ni][1];
                float d2 = (zn[mi * 2 + 1] + en0) - 2.0f * acc[mi][ni][2];
                float d3 = (zn[mi * 2 + 1] + en1) - 2.0f * acc[mi][ni][3];
                if (d0 < b0) { int p = atomicAdd(&g_ncand[shard], 1);
                    if (p < SHARD_CAP) { g_cand[shard][p] = ((row0 + rl0) << 13) | (colg0 + ni * 8);
                                         g_cand_d[shard][p] = d0; } }
                if (d1 < b0) { int p = atomicAdd(&g_ncand[shard], 1);
                    if (p < SHARD_CAP) { g_cand[shard][p] = ((row0 + rl0) << 13) | (colg0 + ni * 8 + 1);
                                         g_cand_d[shard][p] = d1; } }
                if (d2 < b1) { int p = atomicAdd(&g_ncand[shard], 1);
                    if (p < SHARD_CAP) { g_cand[shard][p] = ((row0 + rl1) << 13) | (colg0 + ni * 8);
                                         g_cand_d[shard][p] = d2; } }
                if (d3 < b1) { int p = atomicAdd(&g_ncand[shard], 1);
                    if (p < SHARD_CAP) { g_cand[shard][p] = ((row0 + rl1) << 13) | (colg0 + ni * 8 + 1);
                                         g_cand_d[shard][p] = d3; } }
            }
        }
    }
}

// ---------------------------------------------------------------------------
// Exact fp32 refinement with FINAL-bound pre-pruning.
// ---------------------------------------------------------------------------
__global__ void refine_kernel(const float* __restrict__ Z, const float* __restrict__ E) {
    const int nwarps = (gridDim.x * blockDim.x) >> 5;
    const int gw     = (blockIdx.x * blockDim.x + threadIdx.x) >> 5;
    const int lane   = threadIdx.x & 31;

    for (int s = 0; s < NSHARDS; s++) {
        int n = g_ncand[s];
        if (n > SHARD_CAP) n = SHARD_CAP;
        for (int i = gw; i < n; i += nwarps) {
            int cd  = g_cand[s][i];
            int row = cd >> 13;
            int idx = cd & (K_CODES - 1);
            float dhat  = g_cand_d[s][i];
            float bound = __int_as_float(g_bound[row]);
            if (dhat > bound + MARGIN) continue;

            const float4* z4 = reinterpret_cast<const float4*>(Z + (size_t)row * D_DIM);
            const float4* e4 = reinterpret_cast<const float4*>(E + (size_t)idx * D_DIM);
            float4 zv[4], ev[4];
            #pragma unroll
            for (int j = 0; j < 4; j++) {
                zv[j] = z4[j * 32 + lane];
                ev[j] = e4[j * 32 + lane];
            }
            float dot = 0.0f;
            #pragma unroll
            for (int j = 0; j < 4; j++) {
                dot = fmaf(zv[j].x, ev[j].x, dot);
                dot = fmaf(zv[j].y, ev[j].y, dot);
                dot = fmaf(zv[j].z, ev[j].z, dot);
                dot = fmaf(zv[j].w, ev[j].w, dot);
            }
            #pragma unroll
            for (int o = 16; o > 0; o >>= 1) dot += __shfl_down_sync(0xffffffffu, dot, o);
            if (lane == 0) {
                float d = (g_znorm[row] + g_enorm[idx]) - 2.0f * dot;
                unsigned long long key = ((unsigned long long)__float_as_uint(d) << 32) | (unsigned)idx;
                atomicMin(&g_best[row], key);
            }
        }
    }
}

// ---------------------------------------------------------------------------
// Gather: one warp per row (8 rows per 256-thr block), shfl reduction.
// ---------------------------------------------------------------------------
__global__ void gather_kernel(const float* __restrict__ Z, const float* __restrict__ E,
                              float* __restrict__ out, int out_size) {
    const int row  = blockIdx.x * 8 + (threadIdx.x >> 5);
    const int lane = threadIdx.x & 31;
    int idx = (int)(g_best[row] & 0xFFFFFFFFull) & (K_CODES - 1);
    const float4* e4 = reinterpret_cast<const float4*>(E + (size_t)idx * D_DIM);
    const float4* z4 = reinterpret_cast<const float4*>(Z + (size_t)row * D_DIM);
    float4* o4 = reinterpret_cast<float4*>(out + (size_t)row * D_DIM);

    double s = 0.0;
    #pragma unroll
    for (int j = 0; j < 4; j++) {
        float4 q = e4[j * 32 + lane], zc = z4[j * 32 + lane], dq, o;
        dq.x = q.x - zc.x; dq.y = q.y - zc.y; dq.z = q.z - zc.z; dq.w = q.w - zc.w;
        o.x = zc.x + dq.x; o.y = zc.y + dq.y; o.z = zc.z + dq.z; o.w = zc.w + dq.w;
        o4[j * 32 + lane] = o;
        s += (double)dq.x * dq.x + (double)dq.y * dq.y
           + (double)dq.z * dq.z + (double)dq.w * dq.w;
    }
    #pragma unroll
    for (int o2 = 16; o2 > 0; o2 >>= 1) s += __shfl_down_sync(0xffffffffu, s, o2);
    if (lane == 0) {
        g_rowpart[row] = s;
        if (out_size >= N_ROWS * D_DIM + 1 + N_ROWS)
            out[(size_t)N_ROWS * D_DIM + 1 + row] = (float)idx;
    }
}

__global__ void loss_kernel(float* __restrict__ out, int out_size) {
    __shared__ double sh[1024];
    int t = threadIdx.x;
    double s = 0.0;
    for (int i = t; i < N_ROWS; i += 1024) s += g_rowpart[i];
    sh[t] = s;
    __syncthreads();
    for (int o = 512; o > 0; o >>= 1) { if (t < o) sh[t] += sh[t + o]; __syncthreads(); }
    if (t == 0 && out_size >= N_ROWS * D_DIM + 1) {
        double m = sh[0] / ((double)N_ROWS * (double)D_DIM);
        out[(size_t)N_ROWS * D_DIM] = (float)(1.25 * m);
    }
}

// ---------------------------------------------------------------------------
extern "C" void kernel_launch(void* const* d_in, const int* in_sizes, int n_in,
                              void* d_out, int out_size) {
    const float* z = (const float*)d_in[0];
    const float* e = (const float*)d_in[1];
    if (n_in >= 2 && in_sizes[0] == K_CODES * D_DIM && in_sizes[1] == N_ROWS * D_DIM) {
        const float* tmp = z; z = e; e = tmp;
    }
    float* out = (float*)d_out;

    const int smem_bytes = STAGES * 2 * BM * RSU * 4 + BM * 4;   // 111104
    cudaFuncSetAttribute(vq_mma_kernel, cudaFuncAttributeMaxDynamicSharedMemorySize, smem_bytes);

    int prep_blocks = ((N_ROWS + K_CODES) * 32 + 255) / 256;     // one warp per row
    prep_kernel<<<prep_blocks, 256>>>(z, e);
    vq_mma_kernel<<<(N_ROWS / BM) * KSPLIT, 256, smem_bytes>>>(z, e);
    refine_kernel<<<1024, 256>>>(z, e);
    gather_kernel<<<N_ROWS / 8, 256>>>(z, e, out, out_size);
    loss_kernel<<<1, 1024>>>(out, out_size);
}

// round 16
// speedup vs baseline: 1.8667x; 1.0666x over previous
#include <cuda_runtime.h>
#include <cuda_bf16.h>
#include <cstdint>

#define N_ROWS 32768
#define K_CODES 8192
#define D_DIM 512

#define BM 128
#define BN 128
#define BKE 64              // bf16 k-elems per tile
#define STAGES 3
#define NCHUNKS 64          // K_CODES / BN
#define KSPLIT 8            // chunk-range split for load balance (grid 2048)
#define KITERS 8            // D_DIM / BKE
#define RSU 36              // row stride in uint32 (64/2 + 4 pad) = 144 B
#define MARGIN 1.2e-3f
#define NSHARDS 64
#define SHARD_CAP 65536
#define FLT_MAX_BITS 0x7f7fffff

#define ZPAIRS (N_ROWS * D_DIM / 2)
#define EPAIRS (K_CODES * D_DIM / 2)

// ---------------- scratch (static __device__, no allocs) ----------------
__device__ float  g_znorm[N_ROWS];
__device__ float  g_enorm[K_CODES];
__device__ uint32_t g_zbf[ZPAIRS];   // packed bf16x2
__device__ uint32_t g_ebf[EPAIRS];
__device__ int    g_bound[N_ROWS];   // cross-CTA approx-distance bound (fp32 bits)
__device__ unsigned long long g_best[N_ROWS];
__device__ int    g_cand[NSHARDS][SHARD_CAP];
__device__ float  g_cand_d[NSHARDS][SHARD_CAP];   // approx distance at push time
__device__ int    g_ncand[NSHARDS];
__device__ double g_rowpart[N_ROWS];

// ---------------- helpers ----------------
__device__ __forceinline__ uint32_t smem_u32(const void* p) {
    uint32_t a;
    asm("{ .reg .u64 t; cvta.to.shared.u64 t, %1; cvt.u32.u64 %0, t; }" : "=r"(a) : "l"(p));
    return a;
}
__device__ __forceinline__ void cpasync16(uint32_t dst, const void* src) {
    asm volatile("cp.async.cg.shared.global [%0], [%1], 16;" :: "r"(dst), "l"(src));
}
#define CP_COMMIT() asm volatile("cp.async.commit_group;" ::: "memory")
#define CP_WAITG1() asm volatile("cp.async.wait_group 1;" ::: "memory")
#define CP_WAIT0()  asm volatile("cp.async.wait_group 0;" ::: "memory")

#define LDSM_X4(r0, r1, r2, r3, addr) \
    asm volatile("ldmatrix.sync.aligned.m8n8.x4.shared.b16 {%0,%1,%2,%3}, [%4];" \
        : "=r"(r0), "=r"(r1), "=r"(r2), "=r"(r3) : "r"(addr))

// m16n8k16 bf16 HMMA (sm_80 base feature)
__device__ __forceinline__ void mma_bf16(float* d, const uint32_t* a, const uint32_t* b) {
    asm volatile("mma.sync.aligned.m16n8k16.row.col.f32.bf16.bf16.f32 "
        "{%0,%1,%2,%3}, {%4,%5,%6,%7}, {%8,%9}, {%0,%1,%2,%3};"
        : "+f"(d[0]), "+f"(d[1]), "+f"(d[2]), "+f"(d[3])
        : "r"(a[0]), "r"(a[1]), "r"(a[2]), "r"(a[3]), "r"(b[0]), "r"(b[1]));
}

// ---------------------------------------------------------------------------
// Fused: scratch init + bf16 convert + row norms in one pass.
// ---------------------------------------------------------------------------
__global__ void prep_kernel(const float* __restrict__ Z, const float* __restrict__ E) {
    const int gtid = blockIdx.x * blockDim.x + threadIdx.x;
    if (gtid < N_ROWS) {
        g_best[gtid]  = 0xFFFFFFFFFFFFFFFFULL;
        g_bound[gtid] = FLT_MAX_BITS;
    }
    if (gtid < NSHARDS) g_ncand[gtid] = 0;

    int gw = gtid >> 5;
    int lane = threadIdx.x & 31;
    if (gw >= N_ROWS + K_CODES) return;
    const float2* src;
    uint32_t* dst;
    if (gw < N_ROWS) {
        src = reinterpret_cast<const float2*>(Z + (size_t)gw * D_DIM);
        dst = g_zbf + (size_t)gw * (D_DIM / 2);
    } else {
        int r = gw - N_ROWS;
        src = reinterpret_cast<const float2*>(E + (size_t)r * D_DIM);
        dst = g_ebf + (size_t)r * (D_DIM / 2);
    }
    float acc = 0.0f;
    #pragma unroll
    for (int j = 0; j < 8; j++) {
        float2 v = src[j * 32 + lane];
        acc = fmaf(v.x, v.x, acc);
        acc = fmaf(v.y, v.y, acc);
        __nv_bfloat162 b = __floats2bfloat162_rn(v.x, v.y);
        dst[j * 32 + lane] = *reinterpret_cast<uint32_t*>(&b);
    }
    #pragma unroll
    for (int o = 16; o > 0; o >>= 1) acc += __shfl_down_sync(0xffffffffu, acc, o);
    if (lane == 0) {
        if (gw < N_ROWS) g_znorm[gw] = acc;
        else             g_enorm[gw - N_ROWS] = acc;
    }
}

// ---------------------------------------------------------------------------
// bf16 m16n8k16 GEMM + running per-row best + margin candidate push.
// 128x128 CTA, warp 64x32, 8 warps, 2 CTAs/SM, 3-stage cp.async, KSPLIT=8.
// Cross-CTA atomicMin bound pruning; pushes record d-hat for refine pruning.
// ---------------------------------------------------------------------------
__global__ __launch_bounds__(256, 2)
void vq_mma_kernel(const float* __restrict__, const float* __restrict__) {
    extern __shared__ uint32_t sm_u[];
    int* s_rowbest = reinterpret_cast<int*>(sm_u + STAGES * 2 * BM * RSU);

    const int tid = threadIdx.x;
    const int wid = tid >> 5;
    const int l   = tid & 31;
    const int warp_m = wid >> 2;        // 0..1
    const int warp_n = wid & 3;         // 0..3
    const int l4 = l >> 2;              // 0..7
    const int kc = l & 3;               // 0..3
    const int row0 = (blockIdx.x >> 3) * BM;
    const int c0   = (blockIdx.x & 7) * (NCHUNKS / KSPLIT);
    const int shard = blockIdx.x & (NSHARDS - 1);

    const uint32_t sm_base  = smem_u32(sm_u);
    const int      stage_u  = 2 * BM * RSU;                 // u32 per stage
    const uint32_t stage_b  = (uint32_t)stage_u * 4;
    const uint32_t eoff_b   = (uint32_t)(BM * RSU) * 4;

    const uint32_t a_off = (uint32_t)((warp_m * 64 + (l & 15)) * RSU * 4 + ((l >> 4) * 16));
    const uint32_t b_off = (uint32_t)((warp_n * 32 + (l & 7) + ((l >> 4) << 3)) * RSU * 4
                                      + (((l >> 3) & 1) * 16)) + eoff_b;

    if (tid < BM) s_rowbest[tid] = FLT_MAX_BITS;

    float zn[8];
    #pragma unroll
    for (int mi = 0; mi < 4; mi++)
        #pragma unroll
        for (int hi = 0; hi < 2; hi++)
            zn[mi * 2 + hi] = g_znorm[row0 + warp_m * 64 + mi * 16 + hi * 8 + l4];

    __syncthreads();

    const int DP = D_DIM / 2;   // global row stride in pairs

    for (int c = c0; c < c0 + NCHUNKS / KSPLIT; c++) {
        float acc[4][4][4];
        #pragma unroll
        for (int mi = 0; mi < 4; mi++)
            #pragma unroll
            for (int ni = 0; ni < 4; ni++)
                #pragma unroll
                for (int r = 0; r < 4; r++) acc[mi][ni][r] = 0.0f;

        const uint32_t* Zg0 = g_zbf + (size_t)row0 * DP;
        const uint32_t* Eg0 = g_ebf + (size_t)(c * BN) * DP;

        #pragma unroll
        for (int pre = 0; pre < 2; pre++) {
            const int kp = pre * (BKE / 2);
            const uint32_t zb = sm_base + (uint32_t)pre * stage_b;
            const uint32_t eb = zb + eoff_b;
            #pragma unroll
            for (int i = 0; i < 4; i++) {
                int u = tid + i * 256, r = u >> 3, s = u & 7;
                cpasync16(zb + r * (RSU * 4) + s * 16, Zg0 + (size_t)r * DP + kp + s * 4);
                cpasync16(eb + r * (RSU * 4) + s * 16, Eg0 + (size_t)r * DP + kp + s * 4);
            }
            CP_COMMIT();
        }

        #pragma unroll
        for (int it = 0; it < KITERS; it++) {
            if (it == KITERS - 1) { CP_WAIT0(); } else { CP_WAITG1(); }
            __syncthreads();
            if (it + 2 < KITERS) {
                const int st = (it + 2) % STAGES;
                const int kp = (it + 2) * (BKE / 2);
                const uint32_t zb = sm_base + (uint32_t)st * stage_b;
                const uint32_t eb = zb + eoff_b;
                #pragma unroll
                for (int i = 0; i < 4; i++) {
                    int u = tid + i * 256, r = u >> 3, s = u & 7;
                    cpasync16(zb + r * (RSU * 4) + s * 16, Zg0 + (size_t)r * DP + kp + s * 4);
                    cpasync16(eb + r * (RSU * 4) + s * 16, Eg0 + (size_t)r * DP + kp + s * 4);
                }
                CP_COMMIT();
            }
            const uint32_t stg = sm_base + (uint32_t)(it % STAGES) * stage_b;
            const uint32_t abase = stg + a_off;
            const uint32_t bbase = stg + b_off;
            #pragma unroll
            for (int ks = 0; ks < 4; ks++) {
                uint32_t a[4][4], b[4][2];
                #pragma unroll
                for (int mi = 0; mi < 4; mi++)
                    LDSM_X4(a[mi][0], a[mi][1], a[mi][2], a[mi][3],
                            abase + mi * (16 * RSU * 4) + ks * 32);
                #pragma unroll
                for (int np = 0; np < 2; np++)
                    LDSM_X4(b[2 * np][0], b[2 * np][1], b[2 * np + 1][0], b[2 * np + 1][1],
                            bbase + np * (16 * RSU * 4) + ks * 32);
                #pragma unroll
                for (int mi = 0; mi < 4; mi++)
                    #pragma unroll
                    for (int ni = 0; ni < 4; ni++)
                        mma_bf16(acc[mi][ni], a[mi], b[ni]);
            }
        }

        // ---------- epilogue pass 1: per-row running min + global merge ----------
        const int colg0 = c * BN + warp_n * 32 + kc * 2;
        float dmin[8];
        #pragma unroll
        for (int i = 0; i < 8; i++) dmin[i] = 3.4028235e38f;
        #pragma unroll
        for (int ni = 0; ni < 4; ni++) {
            float en0 = __ldg(&g_enorm[colg0 + ni * 8]);
            float en1 = __ldg(&g_enorm[colg0 + ni * 8 + 1]);
            #pragma unroll
            for (int mi = 0; mi < 4; mi++) {
                float d0 = (zn[mi * 2] + en0)     - 2.0f * acc[mi][ni][0];
                float d1 = (zn[mi * 2] + en1)     - 2.0f * acc[mi][ni][1];
                float d2 = (zn[mi * 2 + 1] + en0) - 2.0f * acc[mi][ni][2];
                float d3 = (zn[mi * 2 + 1] + en1) - 2.0f * acc[mi][ni][3];
                dmin[mi * 2]     = fminf(dmin[mi * 2], fminf(d0, d1));
                dmin[mi * 2 + 1] = fminf(dmin[mi * 2 + 1], fminf(d2, d3));
            }
        }
        #pragma unroll
        for (int i = 0; i < 8; i++) {
            dmin[i] = fminf(dmin[i], __shfl_xor_sync(0xffffffffu, dmin[i], 1));
            dmin[i] = fminf(dmin[i], __shfl_xor_sync(0xffffffffu, dmin[i], 2));
        }
        if (kc == 0) {
            #pragma unroll
            for (int mi = 0; mi < 4; mi++) {
                const int rl0 = warp_m * 64 + mi * 16 + l4;
                const int rl1 = rl0 + 8;
                int b0 = __float_as_int(dmin[mi * 2]);
                int b1 = __float_as_int(dmin[mi * 2 + 1]);
                int og0 = atomicMin(&g_bound[row0 + rl0], b0);
                int og1 = atomicMin(&g_bound[row0 + rl1], b1);
                atomicMin(&s_rowbest[rl0], min(og0, b0));
                atomicMin(&s_rowbest[rl1], min(og1, b1));
            }
        }
        __syncthreads();

        // ---------- epilogue pass 2: margin candidate push (records d-hat) ----------
        #pragma unroll
        for (int ni = 0; ni < 4; ni++) {
            float en0 = __ldg(&g_enorm[colg0 + ni * 8]);
            float en1 = __ldg(&g_enorm[colg0 + ni * 8 + 1]);
            #pragma unroll
            for (int mi = 0; mi < 4; mi++) {
                const int rl0 = warp_m * 64 + mi * 16 + l4;
                const int rl1 = rl0 + 8;
                const float b0 = __int_as_float(s_rowbest[rl0]) + MARGIN;
                const float b1 = __int_as_float(s_rowbest[rl1]) + MARGIN;
                float d0 = (zn[mi * 2] + en0)     - 2.0f * acc[mi][ni][0];
                float d1 = (zn[mi * 2] + en1)     - 2.0f * acc[mi][ni][1];
                float d2 = (zn[mi * 2 + 1] + en0) - 2.0f * acc[mi][ni][2];
                float d3 = (zn[mi * 2 + 1] + en1) - 2.0f * acc[mi][ni][3];
                if (d0 < b0) { int p = atomicAdd(&g_ncand[shard], 1);
                    if (p < SHARD_CAP) { g_cand[shard][p] = ((row0 + rl0) << 13) | (colg0 + ni * 8);
                                         g_cand_d[shard][p] = d0; } }
                if (d1 < b0) { int p = atomicAdd(&g_ncand[shard], 1);
                    if (p < SHARD_CAP) { g_cand[shard][p] = ((row0 + rl0) << 13) | (colg0 + ni * 8 + 1);
                                         g_cand_d[shard][p] = d1; } }
                if (d2 < b1) { int p = atomicAdd(&g_ncand[shard], 1);
                    if (p < SHARD_CAP) { g_cand[shard][p] = ((row0 + rl1) << 13) | (colg0 + ni * 8);
                                         g_cand_d[shard][p] = d2; } }
                if (d3 < b1) { int p = atomicAdd(&g_ncand[shard], 1);
                    if (p < SHARD_CAP) { g_cand[shard][p] = ((row0 + rl1) << 13) | (colg0 + ni * 8 + 1);
                                         g_cand_d[shard][p] = d3; } }
            }
        }
    }
}

// ---------------------------------------------------------------------------
// Exact fp32 refinement with FINAL-bound pre-pruning.
// ---------------------------------------------------------------------------
__global__ void refine_kernel(const float* __restrict__ Z, const float* __restrict__ E) {
    const int nwarps = (gridDim.x * blockDim.x) >> 5;
    const int gw     = (blockIdx.x * blockDim.x + threadIdx.x) >> 5;
    const int lane   = threadIdx.x & 31;

    for (int s = 0; s < NSHARDS; s++) {
        int n = g_ncand[s];
        if (n > SHARD_CAP) n = SHARD_CAP;
        for (int i = gw; i < n; i += nwarps) {
            int cd  = g_cand[s][i];
            int row = cd >> 13;
            int idx = cd & (K_CODES - 1);
            float dhat  = g_cand_d[s][i];
            float bound = __int_as_float(g_bound[row]);
            if (dhat > bound + MARGIN) continue;

            const float4* z4 = reinterpret_cast<const float4*>(Z + (size_t)row * D_DIM);
            const float4* e4 = reinterpret_cast<const float4*>(E + (size_t)idx * D_DIM);
            float4 zv[4], ev[4];
            #pragma unroll
            for (int j = 0; j < 4; j++) {
                zv[j] = z4[j * 32 + lane];
                ev[j] = e4[j * 32 + lane];
            }
            float dot = 0.0f;
            #pragma unroll
            for (int j = 0; j < 4; j++) {
                dot = fmaf(zv[j].x, ev[j].x, dot);
                dot = fmaf(zv[j].y, ev[j].y, dot);
                dot = fmaf(zv[j].z, ev[j].z, dot);
                dot = fmaf(zv[j].w, ev[j].w, dot);
            }
            #pragma unroll
            for (int o = 16; o > 0; o >>= 1) dot += __shfl_down_sync(0xffffffffu, dot, o);
            if (lane == 0) {
                float d = (g_znorm[row] + g_enorm[idx]) - 2.0f * dot;
                unsigned long long key = ((unsigned long long)__float_as_uint(d) << 32) | (unsigned)idx;
                atomicMin(&g_best[row], key);
            }
        }
    }
}

// ---------------------------------------------------------------------------
// Gather: one warp per row; per-row loss partial accumulated in fp32 with
// independent per-j partials (no FP64 dependency chain), promoted to double
// once per warp.
// ---------------------------------------------------------------------------
__global__ void gather_kernel(const float* __restrict__ Z, const float* __restrict__ E,
                              float* __restrict__ out, int out_size) {
    const int row  = blockIdx.x * 8 + (threadIdx.x >> 5);
    const int lane = threadIdx.x & 31;
    int idx = (int)(g_best[row] & 0xFFFFFFFFull) & (K_CODES - 1);
    const float4* e4 = reinterpret_cast<const float4*>(E + (size_t)idx * D_DIM);
    const float4* z4 = reinterpret_cast<const float4*>(Z + (size_t)row * D_DIM);
    float4* o4 = reinterpret_cast<float4*>(out + (size_t)row * D_DIM);

    float sp[4];
    #pragma unroll
    for (int j = 0; j < 4; j++) {
        float4 q = e4[j * 32 + lane], zc = z4[j * 32 + lane], dq, o;
        dq.x = q.x - zc.x; dq.y = q.y - zc.y; dq.z = q.z - zc.z; dq.w = q.w - zc.w;
        o.x = zc.x + dq.x; o.y = zc.y + dq.y; o.z = zc.z + dq.z; o.w = zc.w + dq.w;
        o4[j * 32 + lane] = o;
        sp[j] = fmaf(dq.x, dq.x, fmaf(dq.y, dq.y, fmaf(dq.z, dq.z, dq.w * dq.w)));
    }
    float s = (sp[0] + sp[1]) + (sp[2] + sp[3]);
    #pragma unroll
    for (int o2 = 16; o2 > 0; o2 >>= 1) s += __shfl_down_sync(0xffffffffu, s, o2);
    if (lane == 0) {
        g_rowpart[row] = (double)s;
        if (out_size >= N_ROWS * D_DIM + 1 + N_ROWS)
            out[(size_t)N_ROWS * D_DIM + 1 + row] = (float)idx;
    }
}

__global__ void loss_kernel(float* __restrict__ out, int out_size) {
    __shared__ double sh[1024];
    int t = threadIdx.x;
    double s = 0.0;
    for (int i = t; i < N_ROWS; i += 1024) s += g_rowpart[i];
    sh[t] = s;
    __syncthreads();
    for (int o = 512; o > 0; o >>= 1) { if (t < o) sh[t] += sh[t + o]; __syncthreads(); }
    if (t == 0 && out_size >= N_ROWS * D_DIM + 1) {
        double m = sh[0] / ((double)N_ROWS * (double)D_DIM);
        out[(size_t)N_ROWS * D_DIM] = (float)(1.25 * m);
    }
}

// ---------------------------------------------------------------------------
extern "C" void kernel_launch(void* const* d_in, const int* in_sizes, int n_in,
                              void* d_out, int out_size) {
    const float* z = (const float*)d_in[0];
    const float* e = (const float*)d_in[1];
    if (n_in >= 2 && in_sizes[0] == K_CODES * D_DIM && in_sizes[1] == N_ROWS * D_DIM) {
        const float* tmp = z; z = e; e = tmp;
    }
    float* out = (float*)d_out;

    const int smem_bytes = STAGES * 2 * BM * RSU * 4 + BM * 4;   // 111104
    cudaFuncSetAttribute(vq_mma_kernel, cudaFuncAttributeMaxDynamicSharedMemorySize, smem_bytes);

    int prep_blocks = ((N_ROWS + K_CODES) * 32 + 255) / 256;     // one warp per row
    prep_kernel<<<prep_blocks, 256>>>(z, e);
    vq_mma_kernel<<<(N_ROWS / BM) * KSPLIT, 256, smem_bytes>>>(z, e);
    refine_kernel<<<1024, 256>>>(z, e);
    gather_kernel<<<N_ROWS / 8, 256>>>(z, e, out, out_size);
    loss_kernel<<<1, 1024>>>(out, out_size);
}